// round 1
// baseline (speedup 1.0000x reference)
#include <cuda_runtime.h>

namespace {

constexpr int kB = 16, kC = 64, kH = 128, kW = 128;
constexpr int PA = 65;    // pitch for [128 x 64] fp32 tiles (bank-conflict-free)
constexpr int PE = 129;   // pitch for 128x128 exp(attn) tile
constexpr int NTHR = 256;
constexpr int PLANE = kH * kW;
constexpr int SMEM_FLOATS = 4 * 128 * PA + 128 * PE + 64 * PA + 4 * 128 + 2 * 64 + 2 * 128;

// Load 64x64 weight, fold LN gamma into it, and compute
// t1[j] = sum_c g[c]*W[j][c], t2[j] = sum_c b[c]*W[j][c].
__device__ __forceinline__ void load_weight_fold(
    const float* __restrict__ Wsrc, const float* __restrict__ g,
    const float* __restrict__ bb, float* __restrict__ WB,
    float* __restrict__ t1, float* __restrict__ t2, int tid)
{
  const int j = tid >> 2;          // 64 rows, 4 threads per row
  const int c0 = (tid & 3) * 16;
  float s1 = 0.f, s2 = 0.f;
#pragma unroll
  for (int u = 0; u < 16; u++) {
    const int c = c0 + u;
    const float raw = Wsrc[j * 64 + c];
    const float wf = raw * g[c];
    WB[j * PA + c] = wf;
    s1 += wf;
    s2 += raw * bb[c];
  }
  s1 += __shfl_xor_sync(0xffffffffu, s1, 1);
  s1 += __shfl_xor_sync(0xffffffffu, s1, 2);
  s2 += __shfl_xor_sync(0xffffffffu, s2, 1);
  s2 += __shfl_xor_sync(0xffffffffu, s2, 2);
  if ((tid & 3) == 0) { t1[j] = s1; t2[j] = s2; }
}

__device__ __forceinline__ void load_weight_raw(
    const float* __restrict__ Wsrc, float* __restrict__ WB, int tid)
{
  const int j = tid >> 2;
  const int c0 = (tid & 3) * 16;
#pragma unroll
  for (int u = 0; u < 16; u += 4) {
    const float4 v = *(const float4*)(Wsrc + j * 64 + c0 + u);
    WB[j * PA + c0 + u + 0] = v.x;
    WB[j * PA + c0 + u + 1] = v.y;
    WB[j * PA + c0 + u + 2] = v.z;
    WB[j * PA + c0 + u + 3] = v.w;
  }
}

// C[128][64] = A[128][64] @ WB^T (WB is [j][k]), optional fused-LN epilogue.
template <bool LN>
__device__ __forceinline__ void gemm_xw(
    const float* __restrict__ A, const float* __restrict__ WB,
    float* __restrict__ Cout, int tid,
    const float* __restrict__ mean, const float* __restrict__ rstd,
    const float* __restrict__ t1, const float* __restrict__ t2)
{
  const int rg = (tid & 15) * 8;   // 8 rows per thread
  const int cg = (tid >> 4) * 4;   // 4 cols per thread
  float acc[8][4];
#pragma unroll
  for (int i = 0; i < 8; i++)
#pragma unroll
    for (int j = 0; j < 4; j++) acc[i][j] = 0.f;

#pragma unroll 8
  for (int k = 0; k < 64; k++) {
    float a[8], w[4];
#pragma unroll
    for (int j = 0; j < 4; j++) w[j] = WB[(cg + j) * PA + k];
#pragma unroll
    for (int i = 0; i < 8; i++) a[i] = A[(rg + i) * PA + k];
#pragma unroll
    for (int i = 0; i < 8; i++)
#pragma unroll
      for (int j = 0; j < 4; j++) acc[i][j] = fmaf(a[i], w[j], acc[i][j]);
  }

#pragma unroll
  for (int i = 0; i < 8; i++) {
    if (LN) {
      const float m = mean[rg + i];
      const float rs = rstd[rg + i];
#pragma unroll
      for (int j = 0; j < 4; j++)
        Cout[(rg + i) * PA + cg + j] = rs * (acc[i][j] - m * t1[cg + j]) + t2[cg + j];
    } else {
#pragma unroll
      for (int j = 0; j < 4; j++) Cout[(rg + i) * PA + cg + j] = acc[i][j];
    }
  }
}

__global__ __launch_bounds__(NTHR, 1)
void scam_kernel(const float* __restrict__ x_l, const float* __restrict__ x_h,
                 const float* __restrict__ g1, const float* __restrict__ b1,
                 const float* __restrict__ g2, const float* __restrict__ b2,
                 const float* __restrict__ Wq, const float* __restrict__ Wk,
                 const float* __restrict__ Wv1, const float* __restrict__ Wv2,
                 float* __restrict__ out_l, float* __restrict__ out_h)
{
  extern __shared__ float sm[];
  float* XL    = sm;                 // [128][PA] raw x_l tile (kept for V gemm + residual)
  float* XH    = XL + 128 * PA;
  float* QV1   = XH + 128 * PA;      // q, then reused for v1
  float* KV2   = QV1 + 128 * PA;     // k, then reused for v2
  float* Ebuf  = KV2 + 128 * PA;     // exp(attn) [128][PE]
  float* WB    = Ebuf + 128 * PE;    // weight staging [64][PA]
  float* meanl = WB + 64 * PA;
  float* rstdl = meanl + 128;
  float* meanh = rstdl + 128;
  float* rstdh = meanh + 128;
  float* t1    = rstdh + 128;
  float* t2    = t1 + 64;
  float* invrow = t2 + 64;
  float* invcol = invrow + 128;

  const int tid = threadIdx.x;
  const int bh = blockIdx.x;
  const int b = bh >> 7;
  const int h = bh & 127;
  const size_t planeoff = ((size_t)b * kC * kH + (size_t)h) * kW;

  // ---- Phase A: load x_l/x_h slice [W=128][C=64] (coalesced float4 on w) ----
  for (int i = tid; i < kC * (kW / 4); i += NTHR) {
    const int c = i >> 5;
    const int w4 = (i & 31) * 4;
    const size_t goff = planeoff + (size_t)c * PLANE + w4;
    const float4 vl = *(const float4*)(x_l + goff);
    const float4 vh = *(const float4*)(x_h + goff);
    XL[(w4 + 0) * PA + c] = vl.x;
    XL[(w4 + 1) * PA + c] = vl.y;
    XL[(w4 + 2) * PA + c] = vl.z;
    XL[(w4 + 3) * PA + c] = vl.w;
    XH[(w4 + 0) * PA + c] = vh.x;
    XH[(w4 + 1) * PA + c] = vh.y;
    XH[(w4 + 2) * PA + c] = vh.z;
    XH[(w4 + 3) * PA + c] = vh.w;
  }
  __syncthreads();

  // ---- Phase B: LN stats (one row per thread; 128 rows x 2 tensors) ----
  {
    const int r = tid & 127;
    const float* src = (tid < 128 ? XL : XH) + r * PA;
    float s = 0.f, s2 = 0.f;
#pragma unroll
    for (int c = 0; c < 64; c++) { const float v = src[c]; s += v; s2 = fmaf(v, v, s2); }
    const float m = s * (1.f / 64.f);
    const float var = fmaf(-m, m, s2 * (1.f / 64.f));
    const float rs = rsqrtf(var + 1e-5f);
    if (tid < 128) { meanl[r] = m; rstdl[r] = rs; }
    else           { meanh[r] = m; rstdh[r] = rs; }
  }
  __syncthreads();

  // ---- Q = LN(xl) @ Wq^T (LN folded into epilogue) ----
  load_weight_fold(Wq, g1, b1, WB, t1, t2, tid);
  __syncthreads();
  gemm_xw<true>(XL, WB, QV1, tid, meanl, rstdl, t1, t2);
  __syncthreads();

  // ---- K = LN(xh) @ Wk^T ----
  load_weight_fold(Wk, g2, b2, WB, t1, t2, tid);
  __syncthreads();
  gemm_xw<true>(XH, WB, KV2, tid, meanh, rstdh, t1, t2);
  __syncthreads();

  // ---- E = exp(Q @ K^T / 8) ----
  {
    const int rg = (tid & 15) * 8;   // w
    const int cg = (tid >> 4) * 8;   // v
    float acc[8][8];
#pragma unroll
    for (int i = 0; i < 8; i++)
#pragma unroll
      for (int j = 0; j < 8; j++) acc[i][j] = 0.f;
#pragma unroll 4
    for (int k = 0; k < 64; k++) {
      float qv[8], kv[8];
#pragma unroll
      for (int i = 0; i < 8; i++) qv[i] = QV1[(rg + i) * PA + k];
#pragma unroll
      for (int j = 0; j < 8; j++) kv[j] = KV2[(cg + j) * PA + k];
#pragma unroll
      for (int i = 0; i < 8; i++)
#pragma unroll
        for (int j = 0; j < 8; j++) acc[i][j] = fmaf(qv[i], kv[j], acc[i][j]);
    }
#pragma unroll
    for (int i = 0; i < 8; i++)
#pragma unroll
      for (int j = 0; j < 8; j++)
        Ebuf[(rg + i) * PE + cg + j] = __expf(acc[i][j] * 0.125f);
  }
  __syncthreads();

  // ---- Row & column sums of E (normalizers pulled out of the AV gemms) ----
  if (tid < 128) {
    float s = 0.f;
    const float* row = Ebuf + tid * PE;
#pragma unroll 8
    for (int v = 0; v < 128; v++) s += row[v];
    invrow[tid] = 1.f / s;
  } else {
    const int v = tid - 128;
    float s = 0.f;
#pragma unroll 8
    for (int i = 0; i < 128; i++) s += Ebuf[i * PE + v];
    invcol[v] = 1.f / s;
  }
  // WB free (last read was K gemm, synced) -> stage Wv1 concurrently
  load_weight_raw(Wv1, WB, tid);
  __syncthreads();

  // ---- V1 = xl @ Wv1^T (overwrites Q; attn already consumed it) ----
  gemm_xw<false>(XL, WB, QV1, tid, nullptr, nullptr, nullptr, nullptr);
  __syncthreads();
  load_weight_raw(Wv2, WB, tid);
  __syncthreads();
  // ---- V2 = xh @ Wv2^T (overwrites K) ----
  gemm_xw<false>(XH, WB, KV2, tid, nullptr, nullptr, nullptr, nullptr);
  __syncthreads();

  // ---- out_l = xl + (E/rowsum) @ V2 ; written transposed to [B,C,H,W] ----
  {
    const int rg = (tid & 15) * 8;   // w
    const int cg = (tid >> 4) * 4;   // c
    float acc[8][4];
#pragma unroll
    for (int i = 0; i < 8; i++)
#pragma unroll
      for (int j = 0; j < 4; j++) acc[i][j] = 0.f;
#pragma unroll 4
    for (int v = 0; v < 128; v++) {
      float e[8], wv[4];
#pragma unroll
      for (int i = 0; i < 8; i++) e[i] = Ebuf[(rg + i) * PE + v];
#pragma unroll
      for (int j = 0; j < 4; j++) wv[j] = KV2[v * PA + cg + j];
#pragma unroll
      for (int i = 0; i < 8; i++)
#pragma unroll
        for (int j = 0; j < 4; j++) acc[i][j] = fmaf(e[i], wv[j], acc[i][j]);
    }
#pragma unroll
    for (int j = 0; j < 4; j++) {
      const int c = cg + j;
      float* dst = out_l + planeoff + (size_t)c * PLANE + rg;
      float4 o;
      o.x = XL[(rg + 0) * PA + c] + acc[0][j] * invrow[rg + 0];
      o.y = XL[(rg + 1) * PA + c] + acc[1][j] * invrow[rg + 1];
      o.z = XL[(rg + 2) * PA + c] + acc[2][j] * invrow[rg + 2];
      o.w = XL[(rg + 3) * PA + c] + acc[3][j] * invrow[rg + 3];
      *(float4*)dst = o;
      o.x = XL[(rg + 4) * PA + c] + acc[4][j] * invrow[rg + 4];
      o.y = XL[(rg + 5) * PA + c] + acc[5][j] * invrow[rg + 5];
      o.z = XL[(rg + 6) * PA + c] + acc[6][j] * invrow[rg + 6];
      o.w = XL[(rg + 7) * PA + c] + acc[7][j] * invrow[rg + 7];
      *(float4*)(dst + 4) = o;
    }
  }

  // ---- out_h = xh + (E^T/colsum) @ V1 ----
  {
    const int rg = (tid & 15) * 8;   // w (output row, reads E column w)
    const int cg = (tid >> 4) * 4;   // c
    float acc[8][4];
#pragma unroll
    for (int i = 0; i < 8; i++)
#pragma unroll
      for (int j = 0; j < 4; j++) acc[i][j] = 0.f;
#pragma unroll 4
    for (int v = 0; v < 128; v++) {
      float e[8], wv[4];
#pragma unroll
      for (int i = 0; i < 8; i++) e[i] = Ebuf[v * PE + rg + i];
#pragma unroll
      for (int j = 0; j < 4; j++) wv[j] = QV1[v * PA + cg + j];
#pragma unroll
      for (int i = 0; i < 8; i++)
#pragma unroll
        for (int j = 0; j < 4; j++) acc[i][j] = fmaf(e[i], wv[j], acc[i][j]);
    }
#pragma unroll
    for (int j = 0; j < 4; j++) {
      const int c = cg + j;
      float* dst = out_h + planeoff + (size_t)c * PLANE + rg;
      float4 o;
      o.x = XH[(rg + 0) * PA + c] + acc[0][j] * invcol[rg + 0];
      o.y = XH[(rg + 1) * PA + c] + acc[1][j] * invcol[rg + 1];
      o.z = XH[(rg + 2) * PA + c] + acc[2][j] * invcol[rg + 2];
      o.w = XH[(rg + 3) * PA + c] + acc[3][j] * invcol[rg + 3];
      *(float4*)dst = o;
      o.x = XH[(rg + 4) * PA + c] + acc[4][j] * invcol[rg + 4];
      o.y = XH[(rg + 5) * PA + c] + acc[5][j] * invcol[rg + 5];
      o.z = XH[(rg + 6) * PA + c] + acc[6][j] * invcol[rg + 6];
      o.w = XH[(rg + 7) * PA + c] + acc[7][j] * invcol[rg + 7];
      *(float4*)(dst + 4) = o;
    }
  }
}

}  // namespace

extern "C" void kernel_launch(void* const* d_in, const int* in_sizes, int n_in,
                              void* d_out, int out_size) {
  const float* x_l  = (const float*)d_in[0];
  const float* x_h  = (const float*)d_in[1];
  const float* g1   = (const float*)d_in[2];
  const float* b1   = (const float*)d_in[3];
  const float* g2   = (const float*)d_in[4];
  const float* b2   = (const float*)d_in[5];
  const float* Wq   = (const float*)d_in[6];
  const float* Wk   = (const float*)d_in[7];
  const float* Wv1  = (const float*)d_in[8];
  const float* Wv2  = (const float*)d_in[9];

  float* out   = (float*)d_out;
  float* out_l = out;
  float* out_h = out + (size_t)kB * kC * kH * kW;

  const size_t smem = (size_t)SMEM_FLOATS * sizeof(float);  // ~214 KB
  cudaFuncSetAttribute(scam_kernel, cudaFuncAttributeMaxDynamicSharedMemorySize, (int)smem);
  scam_kernel<<<kB * kH, NTHR, smem>>>(x_l, x_h, g1, b1, g2, b2, Wq, Wk, Wv1, Wv2,
                                       out_l, out_h);
}

// round 2
// speedup vs baseline: 1.0012x; 1.0012x over previous
#include <cuda_runtime.h>

namespace {

constexpr int kB = 16, kC = 64, kH = 128, kW = 128;
constexpr int PA = 65;    // pitch for [128 x 64] fp32 tiles (bank-conflict-free)
constexpr int PE = 129;   // pitch for 128x128 exp(attn) tile
constexpr int NTHR = 256;
constexpr int PLANE = kH * kW;
constexpr int SMEM_FLOATS = 4 * 128 * PA + 128 * PE + 64 * PA + 4 * 128 + 2 * 64 + 2 * 128;

// Load 64x64 weight, fold LN gamma into it, and compute
// t1[j] = sum_c g[c]*W[j][c], t2[j] = sum_c b[c]*W[j][c].
__device__ __forceinline__ void load_weight_fold(
    const float* __restrict__ Wsrc, const float* __restrict__ g,
    const float* __restrict__ bb, float* __restrict__ WB,
    float* __restrict__ t1, float* __restrict__ t2, int tid)
{
  const int j = tid >> 2;          // 64 rows, 4 threads per row
  const int c0 = (tid & 3) * 16;
  float s1 = 0.f, s2 = 0.f;
#pragma unroll
  for (int u = 0; u < 16; u++) {
    const int c = c0 + u;
    const float raw = Wsrc[j * 64 + c];
    const float wf = raw * g[c];
    WB[j * PA + c] = wf;
    s1 += wf;
    s2 += raw * bb[c];
  }
  s1 += __shfl_xor_sync(0xffffffffu, s1, 1);
  s1 += __shfl_xor_sync(0xffffffffu, s1, 2);
  s2 += __shfl_xor_sync(0xffffffffu, s2, 1);
  s2 += __shfl_xor_sync(0xffffffffu, s2, 2);
  if ((tid & 3) == 0) { t1[j] = s1; t2[j] = s2; }
}

__device__ __forceinline__ void load_weight_raw(
    const float* __restrict__ Wsrc, float* __restrict__ WB, int tid)
{
  const int j = tid >> 2;
  const int c0 = (tid & 3) * 16;
#pragma unroll
  for (int u = 0; u < 16; u += 4) {
    const float4 v = *(const float4*)(Wsrc + j * 64 + c0 + u);
    WB[j * PA + c0 + u + 0] = v.x;
    WB[j * PA + c0 + u + 1] = v.y;
    WB[j * PA + c0 + u + 2] = v.z;
    WB[j * PA + c0 + u + 3] = v.w;
  }
}

// C[128][64] = A[128][64] @ WB^T (WB is [j][k]), optional fused-LN epilogue.
template <bool LN>
__device__ __forceinline__ void gemm_xw(
    const float* __restrict__ A, const float* __restrict__ WB,
    float* __restrict__ Cout, int tid,
    const float* __restrict__ mean, const float* __restrict__ rstd,
    const float* __restrict__ t1, const float* __restrict__ t2)
{
  const int rg = (tid & 15) * 8;   // 8 rows per thread
  const int cg = (tid >> 4) * 4;   // 4 cols per thread
  float acc[8][4];
#pragma unroll
  for (int i = 0; i < 8; i++)
#pragma unroll
    for (int j = 0; j < 4; j++) acc[i][j] = 0.f;

#pragma unroll 8
  for (int k = 0; k < 64; k++) {
    float a[8], w[4];
#pragma unroll
    for (int j = 0; j < 4; j++) w[j] = WB[(cg + j) * PA + k];
#pragma unroll
    for (int i = 0; i < 8; i++) a[i] = A[(rg + i) * PA + k];
#pragma unroll
    for (int i = 0; i < 8; i++)
#pragma unroll
      for (int j = 0; j < 4; j++) acc[i][j] = fmaf(a[i], w[j], acc[i][j]);
  }

#pragma unroll
  for (int i = 0; i < 8; i++) {
    if (LN) {
      const float m = mean[rg + i];
      const float rs = rstd[rg + i];
#pragma unroll
      for (int j = 0; j < 4; j++)
        Cout[(rg + i) * PA + cg + j] = rs * (acc[i][j] - m * t1[cg + j]) + t2[cg + j];
    } else {
#pragma unroll
      for (int j = 0; j < 4; j++) Cout[(rg + i) * PA + cg + j] = acc[i][j];
    }
  }
}

__global__ __launch_bounds__(NTHR, 1)
void scam_kernel(const float* __restrict__ x_l, const float* __restrict__ x_h,
                 const float* __restrict__ g1, const float* __restrict__ b1,
                 const float* __restrict__ g2, const float* __restrict__ b2,
                 const float* __restrict__ Wq, const float* __restrict__ Wk,
                 const float* __restrict__ Wv1, const float* __restrict__ Wv2,
                 float* __restrict__ out_l, float* __restrict__ out_h)
{
  extern __shared__ float sm[];
  float* XL    = sm;                 // [128][PA] raw x_l tile (kept for V gemm + residual)
  float* XH    = XL + 128 * PA;
  float* QV1   = XH + 128 * PA;      // q, then reused for v1
  float* KV2   = QV1 + 128 * PA;     // k, then reused for v2
  float* Ebuf  = KV2 + 128 * PA;     // exp(attn) [128][PE]
  float* WB    = Ebuf + 128 * PE;    // weight staging [64][PA]
  float* meanl = WB + 64 * PA;
  float* rstdl = meanl + 128;
  float* meanh = rstdl + 128;
  float* rstdh = meanh + 128;
  float* t1    = rstdh + 128;
  float* t2    = t1 + 64;
  float* invrow = t2 + 64;
  float* invcol = invrow + 128;

  const int tid = threadIdx.x;
  const int bh = blockIdx.x;
  const int b = bh >> 7;
  const int h = bh & 127;
  const size_t planeoff = ((size_t)b * kC * kH + (size_t)h) * kW;

  // ---- Phase A: load x_l/x_h slice [W=128][C=64] (coalesced float4 on w) ----
  for (int i = tid; i < kC * (kW / 4); i += NTHR) {
    const int c = i >> 5;
    const int w4 = (i & 31) * 4;
    const size_t goff = planeoff + (size_t)c * PLANE + w4;
    const float4 vl = *(const float4*)(x_l + goff);
    const float4 vh = *(const float4*)(x_h + goff);
    XL[(w4 + 0) * PA + c] = vl.x;
    XL[(w4 + 1) * PA + c] = vl.y;
    XL[(w4 + 2) * PA + c] = vl.z;
    XL[(w4 + 3) * PA + c] = vl.w;
    XH[(w4 + 0) * PA + c] = vh.x;
    XH[(w4 + 1) * PA + c] = vh.y;
    XH[(w4 + 2) * PA + c] = vh.z;
    XH[(w4 + 3) * PA + c] = vh.w;
  }
  __syncthreads();

  // ---- Phase B: LN stats (one row per thread; 128 rows x 2 tensors) ----
  {
    const int r = tid & 127;
    const float* src = (tid < 128 ? XL : XH) + r * PA;
    float s = 0.f, s2 = 0.f;
#pragma unroll
    for (int c = 0; c < 64; c++) { const float v = src[c]; s += v; s2 = fmaf(v, v, s2); }
    const float m = s * (1.f / 64.f);
    const float var = fmaf(-m, m, s2 * (1.f / 64.f));
    const float rs = rsqrtf(var + 1e-5f);
    if (tid < 128) { meanl[r] = m; rstdl[r] = rs; }
    else           { meanh[r] = m; rstdh[r] = rs; }
  }
  __syncthreads();

  // ---- Q = LN(xl) @ Wq^T (LN folded into epilogue) ----
  load_weight_fold(Wq, g1, b1, WB, t1, t2, tid);
  __syncthreads();
  gemm_xw<true>(XL, WB, QV1, tid, meanl, rstdl, t1, t2);
  __syncthreads();

  // ---- K = LN(xh) @ Wk^T ----
  load_weight_fold(Wk, g2, b2, WB, t1, t2, tid);
  __syncthreads();
  gemm_xw<true>(XH, WB, KV2, tid, meanh, rstdh, t1, t2);
  __syncthreads();

  // ---- E = exp(Q @ K^T / 8) ----
  {
    const int rg = (tid & 15) * 8;   // w
    const int cg = (tid >> 4) * 8;   // v
    float acc[8][8];
#pragma unroll
    for (int i = 0; i < 8; i++)
#pragma unroll
      for (int j = 0; j < 8; j++) acc[i][j] = 0.f;
#pragma unroll 4
    for (int k = 0; k < 64; k++) {
      float qv[8], kv[8];
#pragma unroll
      for (int i = 0; i < 8; i++) qv[i] = QV1[(rg + i) * PA + k];
#pragma unroll
      for (int j = 0; j < 8; j++) kv[j] = KV2[(cg + j) * PA + k];
#pragma unroll
      for (int i = 0; i < 8; i++)
#pragma unroll
        for (int j = 0; j < 8; j++) acc[i][j] = fmaf(qv[i], kv[j], acc[i][j]);
    }
#pragma unroll
    for (int i = 0; i < 8; i++)
#pragma unroll
      for (int j = 0; j < 8; j++)
        Ebuf[(rg + i) * PE + cg + j] = __expf(acc[i][j] * 0.125f);
  }
  __syncthreads();

  // ---- Row & column sums of E (normalizers pulled out of the AV gemms) ----
  if (tid < 128) {
    float s = 0.f;
    const float* row = Ebuf + tid * PE;
#pragma unroll 8
    for (int v = 0; v < 128; v++) s += row[v];
    invrow[tid] = 1.f / s;
  } else {
    const int v = tid - 128;
    float s = 0.f;
#pragma unroll 8
    for (int i = 0; i < 128; i++) s += Ebuf[i * PE + v];
    invcol[v] = 1.f / s;
  }
  // WB free (last read was K gemm, synced) -> stage Wv1 concurrently
  load_weight_raw(Wv1, WB, tid);
  __syncthreads();

  // ---- V1 = xl @ Wv1^T (overwrites Q; attn already consumed it) ----
  gemm_xw<false>(XL, WB, QV1, tid, nullptr, nullptr, nullptr, nullptr);
  __syncthreads();
  load_weight_raw(Wv2, WB, tid);
  __syncthreads();
  // ---- V2 = xh @ Wv2^T (overwrites K) ----
  gemm_xw<false>(XH, WB, KV2, tid, nullptr, nullptr, nullptr, nullptr);
  __syncthreads();

  // ---- out_l = xl + (E/rowsum) @ V2 ; written transposed to [B,C,H,W] ----
  {
    const int rg = (tid & 15) * 8;   // w
    const int cg = (tid >> 4) * 4;   // c
    float acc[8][4];
#pragma unroll
    for (int i = 0; i < 8; i++)
#pragma unroll
      for (int j = 0; j < 4; j++) acc[i][j] = 0.f;
#pragma unroll 4
    for (int v = 0; v < 128; v++) {
      float e[8], wv[4];
#pragma unroll
      for (int i = 0; i < 8; i++) e[i] = Ebuf[(rg + i) * PE + v];
#pragma unroll
      for (int j = 0; j < 4; j++) wv[j] = KV2[v * PA + cg + j];
#pragma unroll
      for (int i = 0; i < 8; i++)
#pragma unroll
        for (int j = 0; j < 4; j++) acc[i][j] = fmaf(e[i], wv[j], acc[i][j]);
    }
#pragma unroll
    for (int j = 0; j < 4; j++) {
      const int c = cg + j;
      float* dst = out_l + planeoff + (size_t)c * PLANE + rg;
      float4 o;
      o.x = XL[(rg + 0) * PA + c] + acc[0][j] * invrow[rg + 0];
      o.y = XL[(rg + 1) * PA + c] + acc[1][j] * invrow[rg + 1];
      o.z = XL[(rg + 2) * PA + c] + acc[2][j] * invrow[rg + 2];
      o.w = XL[(rg + 3) * PA + c] + acc[3][j] * invrow[rg + 3];
      *(float4*)dst = o;
      o.x = XL[(rg + 4) * PA + c] + acc[4][j] * invrow[rg + 4];
      o.y = XL[(rg + 5) * PA + c] + acc[5][j] * invrow[rg + 5];
      o.z = XL[(rg + 6) * PA + c] + acc[6][j] * invrow[rg + 6];
      o.w = XL[(rg + 7) * PA + c] + acc[7][j] * invrow[rg + 7];
      *(float4*)(dst + 4) = o;
    }
  }

  // ---- out_h = xh + (E^T/colsum) @ V1 ----
  {
    const int rg = (tid & 15) * 8;   // w (output row, reads E column w)
    const int cg = (tid >> 4) * 4;   // c
    float acc[8][4];
#pragma unroll
    for (int i = 0; i < 8; i++)
#pragma unroll
      for (int j = 0; j < 4; j++) acc[i][j] = 0.f;
#pragma unroll 4
    for (int v = 0; v < 128; v++) {
      float e[8], wv[4];
#pragma unroll
      for (int i = 0; i < 8; i++) e[i] = Ebuf[v * PE + rg + i];
#pragma unroll
      for (int j = 0; j < 4; j++) wv[j] = QV1[v * PA + cg + j];
#pragma unroll
      for (int i = 0; i < 8; i++)
#pragma unroll
        for (int j = 0; j < 4; j++) acc[i][j] = fmaf(e[i], wv[j], acc[i][j]);
    }
#pragma unroll
    for (int j = 0; j < 4; j++) {
      const int c = cg + j;
      float* dst = out_h + planeoff + (size_t)c * PLANE + rg;
      float4 o;
      o.x = XH[(rg + 0) * PA + c] + acc[0][j] * invcol[rg + 0];
      o.y = XH[(rg + 1) * PA + c] + acc[1][j] * invcol[rg + 1];
      o.z = XH[(rg + 2) * PA + c] + acc[2][j] * invcol[rg + 2];
      o.w = XH[(rg + 3) * PA + c] + acc[3][j] * invcol[rg + 3];
      *(float4*)dst = o;
      o.x = XH[(rg + 4) * PA + c] + acc[4][j] * invcol[rg + 4];
      o.y = XH[(rg + 5) * PA + c] + acc[5][j] * invcol[rg + 5];
      o.z = XH[(rg + 6) * PA + c] + acc[6][j] * invcol[rg + 6];
      o.w = XH[(rg + 7) * PA + c] + acc[7][j] * invcol[rg + 7];
      *(float4*)(dst + 4) = o;
    }
  }
}

}  // namespace

extern "C" void kernel_launch(void* const* d_in, const int* in_sizes, int n_in,
                              void* d_out, int out_size) {
  const float* x_l  = (const float*)d_in[0];
  const float* x_h  = (const float*)d_in[1];
  const float* g1   = (const float*)d_in[2];
  const float* b1   = (const float*)d_in[3];
  const float* g2   = (const float*)d_in[4];
  const float* b2   = (const float*)d_in[5];
  const float* Wq   = (const float*)d_in[6];
  const float* Wk   = (const float*)d_in[7];
  const float* Wv1  = (const float*)d_in[8];
  const float* Wv2  = (const float*)d_in[9];

  float* out   = (float*)d_out;
  float* out_l = out;
  float* out_h = out + (size_t)kB * kC * kH * kW;

  const size_t smem = (size_t)SMEM_FLOATS * sizeof(float);  // ~214 KB
  cudaFuncSetAttribute(scam_kernel, cudaFuncAttributeMaxDynamicSharedMemorySize, (int)smem);
  scam_kernel<<<kB * kH, NTHR, smem>>>(x_l, x_h, g1, b1, g2, b2, Wq, Wk, Wv1, Wv2,
                                       out_l, out_h);
}

// round 3
// speedup vs baseline: 2.4308x; 2.4277x over previous
#include <cuda_runtime.h>
#include <cstdint>

namespace {

constexpr int kB = 16, kC = 64, kH = 128, kW = 128;
constexpr int PX = 68;    // pitch for [128 x 64] tiles; 68 % 32 == 4 -> conflict-free A-frags
constexpr int PE = 132;   // pitch for 128x128 E tile; 132 % 32 == 4
constexpr int NTHR = 256;
constexpr int PLANE = kH * kW;
constexpr int SMEM_FLOATS = 4 * 128 * PX + 128 * PE + 64 * PX + 4 * 128 + 2 * 64 + 2 * 128;

__device__ __forceinline__ uint32_t f2t(float x) {
  uint32_t r;
  asm("cvt.rna.tf32.f32 %0, %1;" : "=r"(r) : "f"(x));
  return r;
}
__device__ __forceinline__ float tround(float x) { return __uint_as_float(f2t(x)); }
__device__ __forceinline__ uint32_t fu(float x) { return __float_as_uint(x); }

__device__ __forceinline__ void mma8(float* c, uint32_t a0, uint32_t a1, uint32_t a2,
                                     uint32_t a3, uint32_t b0, uint32_t b1) {
  asm volatile(
      "mma.sync.aligned.m16n8k8.row.col.f32.tf32.tf32.f32 "
      "{%0,%1,%2,%3},{%4,%5,%6,%7},{%8,%9},{%0,%1,%2,%3};"
      : "+f"(c[0]), "+f"(c[1]), "+f"(c[2]), "+f"(c[3])
      : "r"(a0), "r"(a1), "r"(a2), "r"(a3), "r"(b0), "r"(b1));
}

// Load 64x64 weight, fold LN gamma, round to tf32; t1[j]=sum_c wf, t2[j]=sum_c b*W.
__device__ __forceinline__ void load_weight_fold(
    const float* __restrict__ Wsrc, const float* __restrict__ g,
    const float* __restrict__ bb, float* __restrict__ WB,
    float* __restrict__ t1, float* __restrict__ t2, int tid) {
  const int j = tid >> 2;
  const int c0 = (tid & 3) * 16;
  float s1 = 0.f, s2 = 0.f;
#pragma unroll
  for (int u = 0; u < 16; u++) {
    const int c = c0 + u;
    const float raw = Wsrc[j * 64 + c];
    const float wf = tround(raw * g[c]);
    WB[j * PX + c] = wf;
    s1 += wf;
    s2 += raw * bb[c];
  }
  s1 += __shfl_xor_sync(0xffffffffu, s1, 1);
  s1 += __shfl_xor_sync(0xffffffffu, s1, 2);
  s2 += __shfl_xor_sync(0xffffffffu, s2, 1);
  s2 += __shfl_xor_sync(0xffffffffu, s2, 2);
  if ((tid & 3) == 0) { t1[j] = s1; t2[j] = s2; }
}

__device__ __forceinline__ void load_weight_raw(
    const float* __restrict__ Wsrc, float* __restrict__ WB, int tid) {
  const int j = tid >> 2;
  const int c0 = (tid & 3) * 16;
#pragma unroll
  for (int u = 0; u < 16; u++) WB[j * PX + c0 + u] = tround(Wsrc[j * 64 + c0 + u]);
}

// C[128][64] = A[128][64] @ WB^T via m16n8k8 tf32. A is exact fp32 (cvt inline),
// WB pre-rounded. Optional fused-LN epilogue; result stored tf32-rounded.
template <bool LN>
__device__ __forceinline__ void gemm_xw_mma(
    const float* __restrict__ A, const float* __restrict__ WB, float* __restrict__ C,
    int wid, int qr, int qc, const float* __restrict__ mean,
    const float* __restrict__ rstd, const float* __restrict__ t1,
    const float* __restrict__ t2) {
  const int r0 = (wid & 3) * 32;
  const int c0 = (wid >> 2) * 32;
  float acc[2][4][4];
#pragma unroll
  for (int mi = 0; mi < 2; mi++)
#pragma unroll
    for (int nj = 0; nj < 4; nj++)
#pragma unroll
      for (int e = 0; e < 4; e++) acc[mi][nj][e] = 0.f;

#pragma unroll
  for (int k0 = 0; k0 < 64; k0 += 8) {
    uint32_t af[2][4];
#pragma unroll
    for (int mi = 0; mi < 2; mi++) {
      const float* ap = A + (r0 + mi * 16 + qr) * PX + k0 + qc;
      af[mi][0] = f2t(ap[0]);
      af[mi][1] = f2t(ap[8 * PX]);
      af[mi][2] = f2t(ap[4]);
      af[mi][3] = f2t(ap[8 * PX + 4]);
    }
    uint32_t bf[4][2];
#pragma unroll
    for (int nj = 0; nj < 4; nj++) {
      const float* bp = WB + (c0 + nj * 8 + qr) * PX + k0 + qc;
      bf[nj][0] = fu(bp[0]);
      bf[nj][1] = fu(bp[4]);
    }
#pragma unroll
    for (int mi = 0; mi < 2; mi++)
#pragma unroll
      for (int nj = 0; nj < 4; nj++)
        mma8(acc[mi][nj], af[mi][0], af[mi][1], af[mi][2], af[mi][3], bf[nj][0], bf[nj][1]);
  }

#pragma unroll
  for (int mi = 0; mi < 2; mi++) {
    const int ra = r0 + mi * 16 + qr;
#pragma unroll
    for (int nj = 0; nj < 4; nj++) {
      const int cc = c0 + nj * 8 + 2 * qc;
      float v0 = acc[mi][nj][0], v1 = acc[mi][nj][1];
      float v2 = acc[mi][nj][2], v3 = acc[mi][nj][3];
      if (LN) {
        const float m0 = mean[ra], rs0 = rstd[ra];
        const float m1 = mean[ra + 8], rs1 = rstd[ra + 8];
        const float ta = t1[cc], tb = t1[cc + 1];
        const float ua = t2[cc], ub = t2[cc + 1];
        v0 = rs0 * (v0 - m0 * ta) + ua;
        v1 = rs0 * (v1 - m0 * tb) + ub;
        v2 = rs1 * (v2 - m1 * ta) + ua;
        v3 = rs1 * (v3 - m1 * tb) + ub;
      }
      C[ra * PX + cc] = tround(v0);
      C[ra * PX + cc + 1] = tround(v1);
      C[(ra + 8) * PX + cc] = tround(v2);
      C[(ra + 8) * PX + cc + 1] = tround(v3);
    }
  }
}

// E = exp(Q @ K^T / 8), stored tf32-rounded. Q,K pre-rounded [128][PX].
__device__ __forceinline__ void gemm_s_mma(
    const float* __restrict__ Q, const float* __restrict__ K, float* __restrict__ E,
    int wid, int qr, int qc) {
  const int r0 = (wid & 3) * 32;
  const int c0 = (wid >> 2) * 64;
  float acc[2][8][4];
#pragma unroll
  for (int mi = 0; mi < 2; mi++)
#pragma unroll
    for (int nj = 0; nj < 8; nj++)
#pragma unroll
      for (int e = 0; e < 4; e++) acc[mi][nj][e] = 0.f;

#pragma unroll
  for (int k0 = 0; k0 < 64; k0 += 8) {
    uint32_t af[2][4];
#pragma unroll
    for (int mi = 0; mi < 2; mi++) {
      const float* ap = Q + (r0 + mi * 16 + qr) * PX + k0 + qc;
      af[mi][0] = fu(ap[0]);
      af[mi][1] = fu(ap[8 * PX]);
      af[mi][2] = fu(ap[4]);
      af[mi][3] = fu(ap[8 * PX + 4]);
    }
    uint32_t bf[8][2];
#pragma unroll
    for (int nj = 0; nj < 8; nj++) {
      const float* bp = K + (c0 + nj * 8 + qr) * PX + k0 + qc;
      bf[nj][0] = fu(bp[0]);
      bf[nj][1] = fu(bp[4]);
    }
#pragma unroll
    for (int mi = 0; mi < 2; mi++)
#pragma unroll
      for (int nj = 0; nj < 8; nj++)
        mma8(acc[mi][nj], af[mi][0], af[mi][1], af[mi][2], af[mi][3], bf[nj][0], bf[nj][1]);
  }

#pragma unroll
  for (int mi = 0; mi < 2; mi++) {
    const int ra = r0 + mi * 16 + qr;
#pragma unroll
    for (int nj = 0; nj < 8; nj++) {
      const int cc = c0 + nj * 8 + 2 * qc;
      E[ra * PE + cc] = tround(__expf(0.125f * acc[mi][nj][0]));
      E[ra * PE + cc + 1] = tround(__expf(0.125f * acc[mi][nj][1]));
      E[(ra + 8) * PE + cc] = tround(__expf(0.125f * acc[mi][nj][2]));
      E[(ra + 8) * PE + cc + 1] = tround(__expf(0.125f * acc[mi][nj][3]));
    }
  }
}

// XL[w][c] += invrow[w] * (E @ V2)[w][c]   (M=128,N=64,K=128)
__device__ __forceinline__ void gemm_out_l(
    const float* __restrict__ E, const float* __restrict__ V2, float* __restrict__ XL,
    const float* __restrict__ invrow, int wid, int qr, int qc) {
  const int r0 = (wid & 3) * 32;
  const int c0 = (wid >> 2) * 32;
  float acc[2][4][4];
#pragma unroll
  for (int mi = 0; mi < 2; mi++)
#pragma unroll
    for (int nj = 0; nj < 4; nj++)
#pragma unroll
      for (int e = 0; e < 4; e++) acc[mi][nj][e] = 0.f;

#pragma unroll
  for (int k0 = 0; k0 < 128; k0 += 8) {
    uint32_t af[2][4];
#pragma unroll
    for (int mi = 0; mi < 2; mi++) {
      const float* ap = E + (r0 + mi * 16 + qr) * PE + k0 + qc;
      af[mi][0] = fu(ap[0]);
      af[mi][1] = fu(ap[8 * PE]);
      af[mi][2] = fu(ap[4]);
      af[mi][3] = fu(ap[8 * PE + 4]);
    }
    uint32_t bf[4][2];
#pragma unroll
    for (int nj = 0; nj < 4; nj++) {
      const int cc = c0 + nj * 8 + qr;
      bf[nj][0] = fu(V2[(k0 + qc) * PX + cc]);
      bf[nj][1] = fu(V2[(k0 + qc + 4) * PX + cc]);
    }
#pragma unroll
    for (int mi = 0; mi < 2; mi++)
#pragma unroll
      for (int nj = 0; nj < 4; nj++)
        mma8(acc[mi][nj], af[mi][0], af[mi][1], af[mi][2], af[mi][3], bf[nj][0], bf[nj][1]);
  }

#pragma unroll
  for (int mi = 0; mi < 2; mi++) {
    const int ra = r0 + mi * 16 + qr;
    const float ir0 = invrow[ra], ir1 = invrow[ra + 8];
#pragma unroll
    for (int nj = 0; nj < 4; nj++) {
      const int cc = c0 + nj * 8 + 2 * qc;
      XL[ra * PX + cc] += acc[mi][nj][0] * ir0;
      XL[ra * PX + cc + 1] += acc[mi][nj][1] * ir0;
      XL[(ra + 8) * PX + cc] += acc[mi][nj][2] * ir1;
      XL[(ra + 8) * PX + cc + 1] += acc[mi][nj][3] * ir1;
    }
  }
}

// out_h^T = V1^T @ E (M=64 c, N=128 w, K=128 v); XH[w][c] += invcol[w]*acc.
// Both operands read via transposed fragment addressing from the natural tiles.
__device__ __forceinline__ void gemm_out_h(
    const float* __restrict__ E, const float* __restrict__ V1, float* __restrict__ XH,
    const float* __restrict__ invcol, int wid, int qr, int qc) {
  const int r0 = (wid & 1) * 32;   // c dimension (64)
  const int c0 = (wid >> 1) * 32;  // w dimension (128)
  float acc[2][4][4];
#pragma unroll
  for (int mi = 0; mi < 2; mi++)
#pragma unroll
    for (int nj = 0; nj < 4; nj++)
#pragma unroll
      for (int e = 0; e < 4; e++) acc[mi][nj][e] = 0.f;

#pragma unroll
  for (int k0 = 0; k0 < 128; k0 += 8) {
    uint32_t af[2][4];
#pragma unroll
    for (int mi = 0; mi < 2; mi++) {
      const int rr = r0 + mi * 16 + qr;  // c index
      const float* ap = V1 + (k0 + qc) * PX + rr;
      af[mi][0] = fu(ap[0]);            // (m=rr,   k=k0+qc)
      af[mi][1] = fu(ap[8]);            // (m=rr+8, k=k0+qc)
      af[mi][2] = fu(ap[4 * PX]);       // (m=rr,   k=k0+qc+4)
      af[mi][3] = fu(ap[4 * PX + 8]);   // (m=rr+8, k=k0+qc+4)
    }
    uint32_t bf[4][2];
#pragma unroll
    for (int nj = 0; nj < 4; nj++) {
      const int cc = c0 + nj * 8 + qr;  // w index
      bf[nj][0] = fu(E[(k0 + qc) * PE + cc]);
      bf[nj][1] = fu(E[(k0 + qc + 4) * PE + cc]);
    }
#pragma unroll
    for (int mi = 0; mi < 2; mi++)
#pragma unroll
      for (int nj = 0; nj < 4; nj++)
        mma8(acc[mi][nj], af[mi][0], af[mi][1], af[mi][2], af[mi][3], bf[nj][0], bf[nj][1]);
  }

#pragma unroll
  for (int mi = 0; mi < 2; mi++) {
    const int ra = r0 + mi * 16 + qr;  // c
#pragma unroll
    for (int nj = 0; nj < 4; nj++) {
      const int w0 = c0 + nj * 8 + 2 * qc;
      const int w1 = w0 + 1;
      XH[w0 * PX + ra] += acc[mi][nj][0] * invcol[w0];
      XH[w1 * PX + ra] += acc[mi][nj][1] * invcol[w1];
      XH[w0 * PX + ra + 8] += acc[mi][nj][2] * invcol[w0];
      XH[w1 * PX + ra + 8] += acc[mi][nj][3] * invcol[w1];
    }
  }
}

__global__ __launch_bounds__(NTHR, 1)
void scam_kernel(const float* __restrict__ x_l, const float* __restrict__ x_h,
                 const float* __restrict__ g1, const float* __restrict__ b1,
                 const float* __restrict__ g2, const float* __restrict__ b2,
                 const float* __restrict__ Wq, const float* __restrict__ Wk,
                 const float* __restrict__ Wv1, const float* __restrict__ Wv2,
                 float* __restrict__ out_l, float* __restrict__ out_h) {
  extern __shared__ float sm[];
  float* XL = sm;                    // [128][PX] exact fp32 (residual) -> out_l stage
  float* XH = XL + 128 * PX;         // [128][PX] exact fp32 -> out_h stage
  float* QV1 = XH + 128 * PX;        // Q then V1 (tf32-rounded)
  float* KV2 = QV1 + 128 * PX;       // K then V2 (tf32-rounded)
  float* Ebuf = KV2 + 128 * PX;      // [128][PE] exp(attn), tf32-rounded
  float* WB = Ebuf + 128 * PE;       // [64][PX] weight staging (tf32-rounded)
  float* meanl = WB + 64 * PX;
  float* rstdl = meanl + 128;
  float* meanh = rstdl + 128;
  float* rstdh = meanh + 128;
  float* t1 = rstdh + 128;
  float* t2 = t1 + 64;
  float* invrow = t2 + 64;
  float* invcol = invrow + 128;

  const int tid = threadIdx.x;
  const int lane = tid & 31;
  const int wid = tid >> 5;
  const int qr = lane >> 2;
  const int qc = lane & 3;
  const int bh = blockIdx.x;
  const int b = bh >> 7;
  const int h = bh & 127;
  const size_t planeoff = ((size_t)b * kC * kH + (size_t)h) * kW;

  // ---- load x slices [w][c], coalesced float4 over w ----
  for (int i = tid; i < kC * (kW / 4); i += NTHR) {
    const int c = i >> 5;
    const int w4 = (i & 31) * 4;
    const size_t goff = planeoff + (size_t)c * PLANE + w4;
    const float4 vl = *(const float4*)(x_l + goff);
    const float4 vh = *(const float4*)(x_h + goff);
    XL[(w4 + 0) * PX + c] = vl.x;
    XL[(w4 + 1) * PX + c] = vl.y;
    XL[(w4 + 2) * PX + c] = vl.z;
    XL[(w4 + 3) * PX + c] = vl.w;
    XH[(w4 + 0) * PX + c] = vh.x;
    XH[(w4 + 1) * PX + c] = vh.y;
    XH[(w4 + 2) * PX + c] = vh.z;
    XH[(w4 + 3) * PX + c] = vh.w;
  }
  __syncthreads();

  // ---- LN stats (row per thread) + stage Wq ----
  {
    const int r = tid & 127;
    const float* src = (tid < 128 ? XL : XH) + r * PX;
    float s = 0.f, s2 = 0.f;
#pragma unroll
    for (int c = 0; c < 64; c++) { const float v = src[c]; s += v; s2 = fmaf(v, v, s2); }
    const float m = s * (1.f / 64.f);
    const float var = fmaf(-m, m, s2 * (1.f / 64.f));
    const float rs = rsqrtf(var + 1e-5f);
    if (tid < 128) { meanl[r] = m; rstdl[r] = rs; }
    else           { meanh[r] = m; rstdh[r] = rs; }
  }
  load_weight_fold(Wq, g1, b1, WB, t1, t2, tid);
  __syncthreads();

  gemm_xw_mma<true>(XL, WB, QV1, wid, qr, qc, meanl, rstdl, t1, t2);
  __syncthreads();

  load_weight_fold(Wk, g2, b2, WB, t1, t2, tid);
  __syncthreads();

  gemm_xw_mma<true>(XH, WB, KV2, wid, qr, qc, meanh, rstdh, t1, t2);
  __syncthreads();

  // ---- E = exp(QK^T/8); stage Wv1 in same phase (WB free) ----
  gemm_s_mma(QV1, KV2, Ebuf, wid, qr, qc);
  load_weight_raw(Wv1, WB, tid);
  __syncthreads();

  // ---- row/col sums of E; V1 = XL @ Wv1^T (overwrites Q) ----
  if (tid < 128) {
    float s = 0.f;
    const float* row = Ebuf + tid * PE;
#pragma unroll 8
    for (int v = 0; v < 128; v++) s += row[v];
    invrow[tid] = 1.f / s;
  } else {
    const int v = tid - 128;
    float s = 0.f;
#pragma unroll 8
    for (int i = 0; i < 128; i++) s += Ebuf[i * PE + v];
    invcol[v] = 1.f / s;
  }
  gemm_xw_mma<false>(XL, WB, QV1, wid, qr, qc, nullptr, nullptr, nullptr, nullptr);
  __syncthreads();

  load_weight_raw(Wv2, WB, tid);
  __syncthreads();

  gemm_xw_mma<false>(XH, WB, KV2, wid, qr, qc, nullptr, nullptr, nullptr, nullptr);
  __syncthreads();

  // ---- out_l = xl + rowsoftmax(E) @ V2 ; out_h = xh + colsoftmax(E)^T @ V1 ----
  gemm_out_l(Ebuf, KV2, XL, invrow, wid, qr, qc);
  gemm_out_h(Ebuf, QV1, XH, invcol, wid, qr, qc);
  __syncthreads();

  // ---- coalesced writeout ----
  for (int i = tid; i < kC * (kW / 4); i += NTHR) {
    const int c = i >> 5;
    const int w4 = (i & 31) * 4;
    const size_t goff = planeoff + (size_t)c * PLANE + w4;
    float4 o;
    o.x = XL[(w4 + 0) * PX + c];
    o.y = XL[(w4 + 1) * PX + c];
    o.z = XL[(w4 + 2) * PX + c];
    o.w = XL[(w4 + 3) * PX + c];
    *(float4*)(out_l + goff) = o;
    o.x = XH[(w4 + 0) * PX + c];
    o.y = XH[(w4 + 1) * PX + c];
    o.z = XH[(w4 + 2) * PX + c];
    o.w = XH[(w4 + 3) * PX + c];
    *(float4*)(out_h + goff) = o;
  }
}

}  // namespace

extern "C" void kernel_launch(void* const* d_in, const int* in_sizes, int n_in,
                              void* d_out, int out_size) {
  const float* x_l = (const float*)d_in[0];
  const float* x_h = (const float*)d_in[1];
  const float* g1 = (const float*)d_in[2];
  const float* b1 = (const float*)d_in[3];
  const float* g2 = (const float*)d_in[4];
  const float* b2 = (const float*)d_in[5];
  const float* Wq = (const float*)d_in[6];
  const float* Wk = (const float*)d_in[7];
  const float* Wv1 = (const float*)d_in[8];
  const float* Wv2 = (const float*)d_in[9];

  float* out = (float*)d_out;
  float* out_l = out;
  float* out_h = out + (size_t)kB * kC * kH * kW;

  const size_t smem = (size_t)SMEM_FLOATS * sizeof(float);  // ~222.5 KB
  cudaFuncSetAttribute(scam_kernel, cudaFuncAttributeMaxDynamicSharedMemorySize, (int)smem);
  scam_kernel<<<kB * kH, NTHR, smem>>>(x_l, x_h, g1, b1, g2, b2, Wq, Wk, Wv1, Wv2,
                                       out_l, out_h);
}

// round 4
// speedup vs baseline: 2.4319x; 1.0005x over previous
#include <cuda_runtime.h>
#include <cstdint>

namespace {

constexpr int kB = 16, kC = 64, kH = 128, kW = 128;
constexpr int PX = 68;    // pitch for [128 x 64] tiles; 68 % 32 == 4 -> conflict-free A-frags
constexpr int PE = 132;   // pitch for 128x128 E tile; 132 % 32 == 4
constexpr int NTHR = 512; // 16 warps -> 4 per SMSP for latency hiding
constexpr int PLANE = kH * kW;
constexpr int SMEM_FLOATS = 4 * 128 * PX + 128 * PE + 64 * PX + 4 * 128 + 2 * 64 + 2 * 128;

__device__ __forceinline__ uint32_t f2t(float x) {
  uint32_t r;
  asm("cvt.rna.tf32.f32 %0, %1;" : "=r"(r) : "f"(x));
  return r;
}
__device__ __forceinline__ float tround(float x) { return __uint_as_float(f2t(x)); }
__device__ __forceinline__ uint32_t fu(float x) { return __float_as_uint(x); }

__device__ __forceinline__ void mma8(float* c, uint32_t a0, uint32_t a1, uint32_t a2,
                                     uint32_t a3, uint32_t b0, uint32_t b1) {
  asm volatile(
      "mma.sync.aligned.m16n8k8.row.col.f32.tf32.tf32.f32 "
      "{%0,%1,%2,%3},{%4,%5,%6,%7},{%8,%9},{%0,%1,%2,%3};"
      : "+f"(c[0]), "+f"(c[1]), "+f"(c[2]), "+f"(c[3])
      : "r"(a0), "r"(a1), "r"(a2), "r"(a3), "r"(b0), "r"(b1));
}

// 64x64 weight: fold LN gamma, round tf32; t1[j]=sum_c g*W, t2[j]=sum_c b*W.
// 512 threads: 8 threads per weight row.
__device__ __forceinline__ void load_weight_fold(
    const float* __restrict__ Wsrc, const float* __restrict__ g,
    const float* __restrict__ bb, float* __restrict__ WB,
    float* __restrict__ t1, float* __restrict__ t2, int tid) {
  const int j = tid >> 3;
  const int c0 = (tid & 7) * 8;
  float s1 = 0.f, s2 = 0.f;
#pragma unroll
  for (int u = 0; u < 8; u++) {
    const int c = c0 + u;
    const float raw = Wsrc[j * 64 + c];
    const float wf = tround(raw * g[c]);
    WB[j * PX + c] = wf;
    s1 += wf;
    s2 += raw * bb[c];
  }
  s1 += __shfl_xor_sync(0xffffffffu, s1, 1);
  s1 += __shfl_xor_sync(0xffffffffu, s1, 2);
  s1 += __shfl_xor_sync(0xffffffffu, s1, 4);
  s2 += __shfl_xor_sync(0xffffffffu, s2, 1);
  s2 += __shfl_xor_sync(0xffffffffu, s2, 2);
  s2 += __shfl_xor_sync(0xffffffffu, s2, 4);
  if ((tid & 7) == 0) { t1[j] = s1; t2[j] = s2; }
}

__device__ __forceinline__ void load_weight_raw(
    const float* __restrict__ Wsrc, float* __restrict__ WB, int tid) {
  const int j = tid >> 3;
  const int c0 = (tid & 7) * 8;
#pragma unroll
  for (int u = 0; u < 8; u++) WB[j * PX + c0 + u] = tround(Wsrc[j * 64 + c0 + u]);
}

// C[128][64] = A[128][64] @ WB^T. 16 warps, 32x16 tiles (4x4 grid).
template <bool LN>
__device__ __forceinline__ void gemm_xw_mma(
    const float* __restrict__ A, const float* __restrict__ WB, float* __restrict__ C,
    int wid, int qr, int qc, const float* __restrict__ mean,
    const float* __restrict__ rstd, const float* __restrict__ t1,
    const float* __restrict__ t2) {
  const int r0 = (wid & 3) * 32;
  const int c0 = (wid >> 2) * 16;
  float acc[2][2][4];
#pragma unroll
  for (int mi = 0; mi < 2; mi++)
#pragma unroll
    for (int nj = 0; nj < 2; nj++)
#pragma unroll
      for (int e = 0; e < 4; e++) acc[mi][nj][e] = 0.f;

#pragma unroll
  for (int k0 = 0; k0 < 64; k0 += 8) {
    uint32_t af[2][4];
#pragma unroll
    for (int mi = 0; mi < 2; mi++) {
      const float* ap = A + (r0 + mi * 16 + qr) * PX + k0 + qc;
      af[mi][0] = f2t(ap[0]);
      af[mi][1] = f2t(ap[8 * PX]);
      af[mi][2] = f2t(ap[4]);
      af[mi][3] = f2t(ap[8 * PX + 4]);
    }
    uint32_t bf[2][2];
#pragma unroll
    for (int nj = 0; nj < 2; nj++) {
      const float* bp = WB + (c0 + nj * 8 + qr) * PX + k0 + qc;
      bf[nj][0] = fu(bp[0]);
      bf[nj][1] = fu(bp[4]);
    }
#pragma unroll
    for (int mi = 0; mi < 2; mi++)
#pragma unroll
      for (int nj = 0; nj < 2; nj++)
        mma8(acc[mi][nj], af[mi][0], af[mi][1], af[mi][2], af[mi][3], bf[nj][0], bf[nj][1]);
  }

#pragma unroll
  for (int mi = 0; mi < 2; mi++) {
    const int ra = r0 + mi * 16 + qr;
#pragma unroll
    for (int nj = 0; nj < 2; nj++) {
      const int cc = c0 + nj * 8 + 2 * qc;
      float v0 = acc[mi][nj][0], v1 = acc[mi][nj][1];
      float v2 = acc[mi][nj][2], v3 = acc[mi][nj][3];
      if (LN) {
        const float m0 = mean[ra], rs0 = rstd[ra];
        const float m1 = mean[ra + 8], rs1 = rstd[ra + 8];
        const float ta = t1[cc], tb = t1[cc + 1];
        const float ua = t2[cc], ub = t2[cc + 1];
        v0 = rs0 * (v0 - m0 * ta) + ua;
        v1 = rs0 * (v1 - m0 * tb) + ub;
        v2 = rs1 * (v2 - m1 * ta) + ua;
        v3 = rs1 * (v3 - m1 * tb) + ub;
      }
      C[ra * PX + cc] = tround(v0);
      C[ra * PX + cc + 1] = tround(v1);
      C[(ra + 8) * PX + cc] = tround(v2);
      C[(ra + 8) * PX + cc + 1] = tround(v3);
    }
  }
}

// E = exp(Q @ K^T / 8). 16 warps, 32x32 tiles (4x4 grid).
__device__ __forceinline__ void gemm_s_mma(
    const float* __restrict__ Q, const float* __restrict__ K, float* __restrict__ E,
    int wid, int qr, int qc) {
  const int r0 = (wid & 3) * 32;
  const int c0 = (wid >> 2) * 32;
  float acc[2][4][4];
#pragma unroll
  for (int mi = 0; mi < 2; mi++)
#pragma unroll
    for (int nj = 0; nj < 4; nj++)
#pragma unroll
      for (int e = 0; e < 4; e++) acc[mi][nj][e] = 0.f;

#pragma unroll
  for (int k0 = 0; k0 < 64; k0 += 8) {
    uint32_t af[2][4];
#pragma unroll
    for (int mi = 0; mi < 2; mi++) {
      const float* ap = Q + (r0 + mi * 16 + qr) * PX + k0 + qc;
      af[mi][0] = fu(ap[0]);
      af[mi][1] = fu(ap[8 * PX]);
      af[mi][2] = fu(ap[4]);
      af[mi][3] = fu(ap[8 * PX + 4]);
    }
    uint32_t bf[4][2];
#pragma unroll
    for (int nj = 0; nj < 4; nj++) {
      const float* bp = K + (c0 + nj * 8 + qr) * PX + k0 + qc;
      bf[nj][0] = fu(bp[0]);
      bf[nj][1] = fu(bp[4]);
    }
#pragma unroll
    for (int mi = 0; mi < 2; mi++)
#pragma unroll
      for (int nj = 0; nj < 4; nj++)
        mma8(acc[mi][nj], af[mi][0], af[mi][1], af[mi][2], af[mi][3], bf[nj][0], bf[nj][1]);
  }

#pragma unroll
  for (int mi = 0; mi < 2; mi++) {
    const int ra = r0 + mi * 16 + qr;
#pragma unroll
    for (int nj = 0; nj < 4; nj++) {
      const int cc = c0 + nj * 8 + 2 * qc;
      E[ra * PE + cc] = tround(__expf(0.125f * acc[mi][nj][0]));
      E[ra * PE + cc + 1] = tround(__expf(0.125f * acc[mi][nj][1]));
      E[(ra + 8) * PE + cc] = tround(__expf(0.125f * acc[mi][nj][2]));
      E[(ra + 8) * PE + cc + 1] = tround(__expf(0.125f * acc[mi][nj][3]));
    }
  }
}

// XL[w][c] += invrow[w] * (E @ V2)[w][c]. 16 warps, 32x16 tiles, K=128.
__device__ __forceinline__ void gemm_out_l(
    const float* __restrict__ E, const float* __restrict__ V2, float* __restrict__ XL,
    const float* __restrict__ invrow, int wid, int qr, int qc) {
  const int r0 = (wid & 3) * 32;
  const int c0 = (wid >> 2) * 16;
  float acc[2][2][4];
#pragma unroll
  for (int mi = 0; mi < 2; mi++)
#pragma unroll
    for (int nj = 0; nj < 2; nj++)
#pragma unroll
      for (int e = 0; e < 4; e++) acc[mi][nj][e] = 0.f;

#pragma unroll
  for (int k0 = 0; k0 < 128; k0 += 8) {
    uint32_t af[2][4];
#pragma unroll
    for (int mi = 0; mi < 2; mi++) {
      const float* ap = E + (r0 + mi * 16 + qr) * PE + k0 + qc;
      af[mi][0] = fu(ap[0]);
      af[mi][1] = fu(ap[8 * PE]);
      af[mi][2] = fu(ap[4]);
      af[mi][3] = fu(ap[8 * PE + 4]);
    }
    uint32_t bf[2][2];
#pragma unroll
    for (int nj = 0; nj < 2; nj++) {
      const int cc = c0 + nj * 8 + qr;
      bf[nj][0] = fu(V2[(k0 + qc) * PX + cc]);
      bf[nj][1] = fu(V2[(k0 + qc + 4) * PX + cc]);
    }
#pragma unroll
    for (int mi = 0; mi < 2; mi++)
#pragma unroll
      for (int nj = 0; nj < 2; nj++)
        mma8(acc[mi][nj], af[mi][0], af[mi][1], af[mi][2], af[mi][3], bf[nj][0], bf[nj][1]);
  }

#pragma unroll
  for (int mi = 0; mi < 2; mi++) {
    const int ra = r0 + mi * 16 + qr;
    const float ir0 = invrow[ra], ir1 = invrow[ra + 8];
#pragma unroll
    for (int nj = 0; nj < 2; nj++) {
      const int cc = c0 + nj * 8 + 2 * qc;
      XL[ra * PX + cc] += acc[mi][nj][0] * ir0;
      XL[ra * PX + cc + 1] += acc[mi][nj][1] * ir0;
      XL[(ra + 8) * PX + cc] += acc[mi][nj][2] * ir1;
      XL[(ra + 8) * PX + cc + 1] += acc[mi][nj][3] * ir1;
    }
  }
}

// out_h^T = V1^T @ E (M=64 c, N=128 w, K=128 v). 16 warps, 16x32 tiles (4x4).
__device__ __forceinline__ void gemm_out_h(
    const float* __restrict__ E, const float* __restrict__ V1, float* __restrict__ XH,
    const float* __restrict__ invcol, int wid, int qr, int qc) {
  const int r0 = (wid & 3) * 16;   // c dimension (64)
  const int c0 = (wid >> 2) * 32;  // w dimension (128)
  float acc[4][4];
#pragma unroll
  for (int nj = 0; nj < 4; nj++)
#pragma unroll
    for (int e = 0; e < 4; e++) acc[nj][e] = 0.f;

#pragma unroll
  for (int k0 = 0; k0 < 128; k0 += 8) {
    const int rr = r0 + qr;
    const float* ap = V1 + (k0 + qc) * PX + rr;
    uint32_t a0 = fu(ap[0]);
    uint32_t a1 = fu(ap[8]);
    uint32_t a2 = fu(ap[4 * PX]);
    uint32_t a3 = fu(ap[4 * PX + 8]);
    uint32_t bf[4][2];
#pragma unroll
    for (int nj = 0; nj < 4; nj++) {
      const int cc = c0 + nj * 8 + qr;
      bf[nj][0] = fu(E[(k0 + qc) * PE + cc]);
      bf[nj][1] = fu(E[(k0 + qc + 4) * PE + cc]);
    }
#pragma unroll
    for (int nj = 0; nj < 4; nj++)
      mma8(acc[nj], a0, a1, a2, a3, bf[nj][0], bf[nj][1]);
  }

  const int ra = r0 + qr;
#pragma unroll
  for (int nj = 0; nj < 4; nj++) {
    const int w0 = c0 + nj * 8 + 2 * qc;
    const int w1 = w0 + 1;
    XH[w0 * PX + ra] += acc[nj][0] * invcol[w0];
    XH[w1 * PX + ra] += acc[nj][1] * invcol[w1];
    XH[w0 * PX + ra + 8] += acc[nj][2] * invcol[w0];
    XH[w1 * PX + ra + 8] += acc[nj][3] * invcol[w1];
  }
}

__global__ __launch_bounds__(NTHR, 1)
void scam_kernel(const float* __restrict__ x_l, const float* __restrict__ x_h,
                 const float* __restrict__ g1, const float* __restrict__ b1,
                 const float* __restrict__ g2, const float* __restrict__ b2,
                 const float* __restrict__ Wq, const float* __restrict__ Wk,
                 const float* __restrict__ Wv1, const float* __restrict__ Wv2,
                 float* __restrict__ out_l, float* __restrict__ out_h) {
  extern __shared__ float sm[];
  float* XL = sm;                    // [128][PX] exact fp32 (residual) -> out_l stage
  float* XH = XL + 128 * PX;
  float* QV1 = XH + 128 * PX;        // Q then V1 (tf32-rounded)
  float* KV2 = QV1 + 128 * PX;       // K then V2
  float* Ebuf = KV2 + 128 * PX;      // [128][PE] exp(attn)
  float* WB = Ebuf + 128 * PE;       // [64][PX] weight staging
  float* meanl = WB + 64 * PX;
  float* rstdl = meanl + 128;
  float* meanh = rstdl + 128;
  float* rstdh = meanh + 128;
  float* t1 = rstdh + 128;
  float* t2 = t1 + 64;
  float* invrow = t2 + 64;
  float* invcol = invrow + 128;

  const int tid = threadIdx.x;
  const int lane = tid & 31;
  const int wid = tid >> 5;
  const int qr = lane >> 2;
  const int qc = lane & 3;
  const int bh = blockIdx.x;
  const int b = bh >> 7;
  const int h = bh & 127;
  const size_t planeoff = ((size_t)b * kC * kH + (size_t)h) * kW;

  // ---- load x slices [w][c], coalesced float4 over w ----
  for (int i = tid; i < kC * (kW / 4); i += NTHR) {
    const int c = i >> 5;
    const int w4 = (i & 31) * 4;
    const size_t goff = planeoff + (size_t)c * PLANE + w4;
    const float4 vl = *(const float4*)(x_l + goff);
    const float4 vh = *(const float4*)(x_h + goff);
    XL[(w4 + 0) * PX + c] = vl.x;
    XL[(w4 + 1) * PX + c] = vl.y;
    XL[(w4 + 2) * PX + c] = vl.z;
    XL[(w4 + 3) * PX + c] = vl.w;
    XH[(w4 + 0) * PX + c] = vh.x;
    XH[(w4 + 1) * PX + c] = vh.y;
    XH[(w4 + 2) * PX + c] = vh.z;
    XH[(w4 + 3) * PX + c] = vh.w;
  }
  __syncthreads();

  // ---- LN stats (2 threads per row, 256 rows) + stage Wq ----
  {
    const int r = (tid >> 1) & 127;
    const int half = tid & 1;
    const float* src = ((tid >> 1) < 128 ? XL : XH) + r * PX + half * 32;
    float s = 0.f, s2 = 0.f;
#pragma unroll
    for (int c = 0; c < 32; c++) { const float v = src[c]; s += v; s2 = fmaf(v, v, s2); }
    s += __shfl_xor_sync(0xffffffffu, s, 1);
    s2 += __shfl_xor_sync(0xffffffffu, s2, 1);
    if (half == 0) {
      const float m = s * (1.f / 64.f);
      const float var = fmaf(-m, m, s2 * (1.f / 64.f));
      const float rs = rsqrtf(var + 1e-5f);
      if ((tid >> 1) < 128) { meanl[r] = m; rstdl[r] = rs; }
      else                  { meanh[r] = m; rstdh[r] = rs; }
    }
  }
  load_weight_fold(Wq, g1, b1, WB, t1, t2, tid);
  __syncthreads();

  gemm_xw_mma<true>(XL, WB, QV1, wid, qr, qc, meanl, rstdl, t1, t2);
  __syncthreads();

  load_weight_fold(Wk, g2, b2, WB, t1, t2, tid);
  __syncthreads();

  gemm_xw_mma<true>(XH, WB, KV2, wid, qr, qc, meanh, rstdh, t1, t2);
  __syncthreads();

  // ---- E = exp(QK^T/8); stage Wv1 in same phase ----
  gemm_s_mma(QV1, KV2, Ebuf, wid, qr, qc);
  load_weight_raw(Wv1, WB, tid);
  __syncthreads();

  // ---- row/col sums of E (2 threads per sum); V1 = XL @ Wv1^T ----
  {
    const int s_idx = tid >> 1;       // 0..255
    const int half = tid & 1;
    float s = 0.f;
    if (s_idx < 128) {
      const float* row = Ebuf + s_idx * PE + half * 64;
#pragma unroll 8
      for (int v = 0; v < 64; v++) s += row[v];
    } else {
      const int v = s_idx - 128;
      const float* col = Ebuf + half * 64 * PE + v;
#pragma unroll 8
      for (int i = 0; i < 64; i++) s += col[i * PE];
    }
    s += __shfl_xor_sync(0xffffffffu, s, 1);
    if (half == 0) {
      if (s_idx < 128) invrow[s_idx] = 1.f / s;
      else             invcol[s_idx - 128] = 1.f / s;
    }
  }
  gemm_xw_mma<false>(XL, WB, QV1, wid, qr, qc, nullptr, nullptr, nullptr, nullptr);
  __syncthreads();

  load_weight_raw(Wv2, WB, tid);
  __syncthreads();

  gemm_xw_mma<false>(XH, WB, KV2, wid, qr, qc, nullptr, nullptr, nullptr, nullptr);
  __syncthreads();

  // ---- out gemms (independent, same phase) ----
  gemm_out_l(Ebuf, KV2, XL, invrow, wid, qr, qc);
  gemm_out_h(Ebuf, QV1, XH, invcol, wid, qr, qc);
  __syncthreads();

  // ---- coalesced writeout ----
  for (int i = tid; i < kC * (kW / 4); i += NTHR) {
    const int c = i >> 5;
    const int w4 = (i & 31) * 4;
    const size_t goff = planeoff + (size_t)c * PLANE + w4;
    float4 o;
    o.x = XL[(w4 + 0) * PX + c];
    o.y = XL[(w4 + 1) * PX + c];
    o.z = XL[(w4 + 2) * PX + c];
    o.w = XL[(w4 + 3) * PX + c];
    *(float4*)(out_l + goff) = o;
    o.x = XH[(w4 + 0) * PX + c];
    o.y = XH[(w4 + 1) * PX + c];
    o.z = XH[(w4 + 2) * PX + c];
    o.w = XH[(w4 + 3) * PX + c];
    *(float4*)(out_h + goff) = o;
  }
}

}  // namespace

extern "C" void kernel_launch(void* const* d_in, const int* in_sizes, int n_in,
                              void* d_out, int out_size) {
  const float* x_l = (const float*)d_in[0];
  const float* x_h = (const float*)d_in[1];
  const float* g1 = (const float*)d_in[2];
  const float* b1 = (const float*)d_in[3];
  const float* g2 = (const float*)d_in[4];
  const float* b2 = (const float*)d_in[5];
  const float* Wq = (const float*)d_in[6];
  const float* Wk = (const float*)d_in[7];
  const float* Wv1 = (const float*)d_in[8];
  const float* Wv2 = (const float*)d_in[9];

  float* out = (float*)d_out;
  float* out_l = out;
  float* out_h = out + (size_t)kB * kC * kH * kW;

  const size_t smem = (size_t)SMEM_FLOATS * sizeof(float);  // ~222.6 KB
  cudaFuncSetAttribute(scam_kernel, cudaFuncAttributeMaxDynamicSharedMemorySize, (int)smem);
  scam_kernel<<<kB * kH, NTHR, smem>>>(x_l, x_h, g1, b1, g2, b2, Wq, Wk, Wv1, Wv2,
                                       out_l, out_h);
}

// round 5
// speedup vs baseline: 2.9914x; 1.2301x over previous
#include <cuda_runtime.h>
#include <cstdint>

namespace {

constexpr int kB = 16, kC = 64, kH = 128, kW = 128;
constexpr int PX = 68;    // pitch for w-major [128 x 64] tiles (Q/K/V); 68 % 32 == 4
constexpr int PE = 132;   // pitch for 128x128 E tile; 132 % 32 == 4
constexpr int PW = 136;   // pitch for c-major [64 x 128] x/out tiles; 136 % 32 == 8
constexpr int NTHR = 512;
constexpr int PLANE = kH * kW;
constexpr int SMEM_FLOATS =
    2 * 64 * PW + 2 * 128 * PX + 128 * PE + 64 * PX + 4 * 128 + 2 * 64 + 2 * 128;

__device__ __forceinline__ uint32_t f2t(float x) {
  uint32_t r;
  asm("cvt.rna.tf32.f32 %0, %1;" : "=r"(r) : "f"(x));
  return r;
}
__device__ __forceinline__ float tround(float x) { return __uint_as_float(f2t(x)); }
__device__ __forceinline__ uint32_t fu(float x) { return __float_as_uint(x); }

__device__ __forceinline__ void mma8(float* c, uint32_t a0, uint32_t a1, uint32_t a2,
                                     uint32_t a3, uint32_t b0, uint32_t b1) {
  asm volatile(
      "mma.sync.aligned.m16n8k8.row.col.f32.tf32.tf32.f32 "
      "{%0,%1,%2,%3},{%4,%5,%6,%7},{%8,%9},{%0,%1,%2,%3};"
      : "+f"(c[0]), "+f"(c[1]), "+f"(c[2]), "+f"(c[3])
      : "r"(a0), "r"(a1), "r"(a2), "r"(a3), "r"(b0), "r"(b1));
}

// 64x64 weight: fold LN gamma, round tf32; t1[j]=sum_c g*W, t2[j]=sum_c b*W.
__device__ __forceinline__ void load_weight_fold(
    const float* __restrict__ Wsrc, const float* __restrict__ g,
    const float* __restrict__ bb, float* __restrict__ WB,
    float* __restrict__ t1, float* __restrict__ t2, int tid) {
  const int j = tid >> 3;
  const int c0 = (tid & 7) * 8;
  float s1 = 0.f, s2 = 0.f;
#pragma unroll
  for (int u = 0; u < 8; u++) {
    const int c = c0 + u;
    const float raw = Wsrc[j * 64 + c];
    const float wf = tround(raw * g[c]);
    WB[j * PX + c] = wf;
    s1 += wf;
    s2 += raw * bb[c];
  }
  s1 += __shfl_xor_sync(0xffffffffu, s1, 1);
  s1 += __shfl_xor_sync(0xffffffffu, s1, 2);
  s1 += __shfl_xor_sync(0xffffffffu, s1, 4);
  s2 += __shfl_xor_sync(0xffffffffu, s2, 1);
  s2 += __shfl_xor_sync(0xffffffffu, s2, 2);
  s2 += __shfl_xor_sync(0xffffffffu, s2, 4);
  if ((tid & 7) == 0) { t1[j] = s1; t2[j] = s2; }
}

__device__ __forceinline__ void load_weight_raw(
    const float* __restrict__ Wsrc, float* __restrict__ WB, int tid) {
  const int j = tid >> 3;
  const int c0 = (tid & 7) * 8;
#pragma unroll
  for (int u = 0; u < 8; u++) WB[j * PX + c0 + u] = tround(Wsrc[j * 64 + c0 + u]);
}

// C[128][64] = A @ WB^T; A is c-major [c][PW] read via transposed fragment
// addressing (conflict-free: bank = 8*qc + qr). C stored w-major [w][PX].
template <bool LN>
__device__ __forceinline__ void gemm_xw_mma(
    const float* __restrict__ A, const float* __restrict__ WB, float* __restrict__ C,
    int wid, int qr, int qc, const float* __restrict__ mean,
    const float* __restrict__ rstd, const float* __restrict__ t1,
    const float* __restrict__ t2) {
  const int r0 = (wid & 3) * 32;
  const int c0 = (wid >> 2) * 16;
  float acc[2][2][4];
#pragma unroll
  for (int mi = 0; mi < 2; mi++)
#pragma unroll
    for (int nj = 0; nj < 2; nj++)
#pragma unroll
      for (int e = 0; e < 4; e++) acc[mi][nj][e] = 0.f;

#pragma unroll
  for (int k0 = 0; k0 < 64; k0 += 8) {
    uint32_t af[2][4];
#pragma unroll
    for (int mi = 0; mi < 2; mi++) {
      // element (w = r0+mi*16+qr(+8), c = k0+qc(+4)) at A[c*PW + w]
      const float* ap = A + (k0 + qc) * PW + r0 + mi * 16 + qr;
      af[mi][0] = f2t(ap[0]);
      af[mi][1] = f2t(ap[8]);
      af[mi][2] = f2t(ap[4 * PW]);
      af[mi][3] = f2t(ap[4 * PW + 8]);
    }
    uint32_t bf[2][2];
#pragma unroll
    for (int nj = 0; nj < 2; nj++) {
      const float* bp = WB + (c0 + nj * 8 + qr) * PX + k0 + qc;
      bf[nj][0] = fu(bp[0]);
      bf[nj][1] = fu(bp[4]);
    }
#pragma unroll
    for (int mi = 0; mi < 2; mi++)
#pragma unroll
      for (int nj = 0; nj < 2; nj++)
        mma8(acc[mi][nj], af[mi][0], af[mi][1], af[mi][2], af[mi][3], bf[nj][0], bf[nj][1]);
  }

#pragma unroll
  for (int mi = 0; mi < 2; mi++) {
    const int ra = r0 + mi * 16 + qr;
#pragma unroll
    for (int nj = 0; nj < 2; nj++) {
      const int cc = c0 + nj * 8 + 2 * qc;
      float v0 = acc[mi][nj][0], v1 = acc[mi][nj][1];
      float v2 = acc[mi][nj][2], v3 = acc[mi][nj][3];
      if (LN) {
        const float m0 = mean[ra], rs0 = rstd[ra];
        const float m1 = mean[ra + 8], rs1 = rstd[ra + 8];
        const float ta = t1[cc], tb = t1[cc + 1];
        const float ua = t2[cc], ub = t2[cc + 1];
        v0 = rs0 * (v0 - m0 * ta) + ua;
        v1 = rs0 * (v1 - m0 * tb) + ub;
        v2 = rs1 * (v2 - m1 * ta) + ua;
        v3 = rs1 * (v3 - m1 * tb) + ub;
      }
      C[ra * PX + cc] = tround(v0);
      C[ra * PX + cc + 1] = tround(v1);
      C[(ra + 8) * PX + cc] = tround(v2);
      C[(ra + 8) * PX + cc + 1] = tround(v3);
    }
  }
}

// E = exp(Q @ K^T / 8). Q,K w-major [w][PX].
__device__ __forceinline__ void gemm_s_mma(
    const float* __restrict__ Q, const float* __restrict__ K, float* __restrict__ E,
    int wid, int qr, int qc) {
  const int r0 = (wid & 3) * 32;
  const int c0 = (wid >> 2) * 32;
  float acc[2][4][4];
#pragma unroll
  for (int mi = 0; mi < 2; mi++)
#pragma unroll
    for (int nj = 0; nj < 4; nj++)
#pragma unroll
      for (int e = 0; e < 4; e++) acc[mi][nj][e] = 0.f;

#pragma unroll
  for (int k0 = 0; k0 < 64; k0 += 8) {
    uint32_t af[2][4];
#pragma unroll
    for (int mi = 0; mi < 2; mi++) {
      const float* ap = Q + (r0 + mi * 16 + qr) * PX + k0 + qc;
      af[mi][0] = fu(ap[0]);
      af[mi][1] = fu(ap[8 * PX]);
      af[mi][2] = fu(ap[4]);
      af[mi][3] = fu(ap[8 * PX + 4]);
    }
    uint32_t bf[4][2];
#pragma unroll
    for (int nj = 0; nj < 4; nj++) {
      const float* bp = K + (c0 + nj * 8 + qr) * PX + k0 + qc;
      bf[nj][0] = fu(bp[0]);
      bf[nj][1] = fu(bp[4]);
    }
#pragma unroll
    for (int mi = 0; mi < 2; mi++)
#pragma unroll
      for (int nj = 0; nj < 4; nj++)
        mma8(acc[mi][nj], af[mi][0], af[mi][1], af[mi][2], af[mi][3], bf[nj][0], bf[nj][1]);
  }

#pragma unroll
  for (int mi = 0; mi < 2; mi++) {
    const int ra = r0 + mi * 16 + qr;
#pragma unroll
    for (int nj = 0; nj < 4; nj++) {
      const int cc = c0 + nj * 8 + 2 * qc;
      E[ra * PE + cc] = tround(__expf(0.125f * acc[mi][nj][0]));
      E[ra * PE + cc + 1] = tround(__expf(0.125f * acc[mi][nj][1]));
      E[(ra + 8) * PE + cc] = tround(__expf(0.125f * acc[mi][nj][2]));
      E[(ra + 8) * PE + cc + 1] = tround(__expf(0.125f * acc[mi][nj][3]));
    }
  }
}

// XL[c][w] += invrow[w] * (E @ V2)[w][c]. XL c-major, V2 w-major.
__device__ __forceinline__ void gemm_out_l(
    const float* __restrict__ E, const float* __restrict__ V2, float* __restrict__ XL,
    const float* __restrict__ invrow, int wid, int qr, int qc) {
  const int r0 = (wid & 3) * 32;
  const int c0 = (wid >> 2) * 16;
  float acc[2][2][4];
#pragma unroll
  for (int mi = 0; mi < 2; mi++)
#pragma unroll
    for (int nj = 0; nj < 2; nj++)
#pragma unroll
      for (int e = 0; e < 4; e++) acc[mi][nj][e] = 0.f;

#pragma unroll
  for (int k0 = 0; k0 < 128; k0 += 8) {
    uint32_t af[2][4];
#pragma unroll
    for (int mi = 0; mi < 2; mi++) {
      const float* ap = E + (r0 + mi * 16 + qr) * PE + k0 + qc;
      af[mi][0] = fu(ap[0]);
      af[mi][1] = fu(ap[8 * PE]);
      af[mi][2] = fu(ap[4]);
      af[mi][3] = fu(ap[8 * PE + 4]);
    }
    uint32_t bf[2][2];
#pragma unroll
    for (int nj = 0; nj < 2; nj++) {
      const int cc = c0 + nj * 8 + qr;
      bf[nj][0] = fu(V2[(k0 + qc) * PX + cc]);
      bf[nj][1] = fu(V2[(k0 + qc + 4) * PX + cc]);
    }
#pragma unroll
    for (int mi = 0; mi < 2; mi++)
#pragma unroll
      for (int nj = 0; nj < 2; nj++)
        mma8(acc[mi][nj], af[mi][0], af[mi][1], af[mi][2], af[mi][3], bf[nj][0], bf[nj][1]);
  }

#pragma unroll
  for (int mi = 0; mi < 2; mi++) {
    const int ra = r0 + mi * 16 + qr;
    const float ir0 = invrow[ra], ir1 = invrow[ra + 8];
#pragma unroll
    for (int nj = 0; nj < 2; nj++) {
      const int cc = c0 + nj * 8 + 2 * qc;
      XL[cc * PW + ra] += acc[mi][nj][0] * ir0;
      XL[(cc + 1) * PW + ra] += acc[mi][nj][1] * ir0;
      XL[cc * PW + ra + 8] += acc[mi][nj][2] * ir1;
      XL[(cc + 1) * PW + ra + 8] += acc[mi][nj][3] * ir1;
    }
  }
}

// out_h^T = V1^T @ E (M=64 c, N=128 w). XH c-major, V1 w-major.
__device__ __forceinline__ void gemm_out_h(
    const float* __restrict__ E, const float* __restrict__ V1, float* __restrict__ XH,
    const float* __restrict__ invcol, int wid, int qr, int qc) {
  const int r0 = (wid & 3) * 16;   // c dimension (64)
  const int c0 = (wid >> 2) * 32;  // w dimension (128)
  float acc[4][4];
#pragma unroll
  for (int nj = 0; nj < 4; nj++)
#pragma unroll
    for (int e = 0; e < 4; e++) acc[nj][e] = 0.f;

#pragma unroll
  for (int k0 = 0; k0 < 128; k0 += 8) {
    const int rr = r0 + qr;
    const float* ap = V1 + (k0 + qc) * PX + rr;
    uint32_t a0 = fu(ap[0]);
    uint32_t a1 = fu(ap[8]);
    uint32_t a2 = fu(ap[4 * PX]);
    uint32_t a3 = fu(ap[4 * PX + 8]);
    uint32_t bf[4][2];
#pragma unroll
    for (int nj = 0; nj < 4; nj++) {
      const int cc = c0 + nj * 8 + qr;
      bf[nj][0] = fu(E[(k0 + qc) * PE + cc]);
      bf[nj][1] = fu(E[(k0 + qc + 4) * PE + cc]);
    }
#pragma unroll
    for (int nj = 0; nj < 4; nj++)
      mma8(acc[nj], a0, a1, a2, a3, bf[nj][0], bf[nj][1]);
  }

  const int ra = r0 + qr;  // c
#pragma unroll
  for (int nj = 0; nj < 4; nj++) {
    const int w0 = c0 + nj * 8 + 2 * qc;
    const int w1 = w0 + 1;
    XH[ra * PW + w0] += acc[nj][0] * invcol[w0];
    XH[ra * PW + w1] += acc[nj][1] * invcol[w1];
    XH[(ra + 8) * PW + w0] += acc[nj][2] * invcol[w0];
    XH[(ra + 8) * PW + w1] += acc[nj][3] * invcol[w1];
  }
}

__global__ __launch_bounds__(NTHR, 1)
void scam_kernel(const float* __restrict__ x_l, const float* __restrict__ x_h,
                 const float* __restrict__ g1, const float* __restrict__ b1,
                 const float* __restrict__ g2, const float* __restrict__ b2,
                 const float* __restrict__ Wq, const float* __restrict__ Wk,
                 const float* __restrict__ Wv1, const float* __restrict__ Wv2,
                 float* __restrict__ out_l, float* __restrict__ out_h) {
  extern __shared__ float sm[];
  float* XL = sm;                    // [64][PW] c-major, exact fp32, residual + out stage
  float* XH = XL + 64 * PW;
  float* QV1 = XH + 64 * PW;         // [128][PX] w-major: Q then V1 (tf32)
  float* KV2 = QV1 + 128 * PX;       // K then V2
  float* Ebuf = KV2 + 128 * PX;      // [128][PE] exp(attn)
  float* WB = Ebuf + 128 * PE;       // [64][PX] weight staging
  float* meanl = WB + 64 * PX;
  float* rstdl = meanl + 128;
  float* meanh = rstdl + 128;
  float* rstdh = meanh + 128;
  float* t1 = rstdh + 128;
  float* t2 = t1 + 64;
  float* invrow = t2 + 64;
  float* invcol = invrow + 128;

  const int tid = threadIdx.x;
  const int lane = tid & 31;
  const int wid = tid >> 5;
  const int qr = lane >> 2;
  const int qc = lane & 3;
  const int bh = blockIdx.x;
  const int b = bh >> 7;
  const int h = bh & 127;
  const size_t planeoff = ((size_t)b * kC * kH + (size_t)h) * kW;

  // ---- load x slices, c-major staging: direct float4 STS, conflict-free ----
  for (int i = tid; i < kC * (kW / 4); i += NTHR) {
    const int c = i >> 5;
    const int w4 = (i & 31) * 4;
    const size_t goff = planeoff + (size_t)c * PLANE + w4;
    *(float4*)(XL + c * PW + w4) = *(const float4*)(x_l + goff);
    *(float4*)(XH + c * PW + w4) = *(const float4*)(x_h + goff);
  }
  __syncthreads();

  // ---- LN stats (2 threads per w-row, strided over c) + stage Wq ----
  {
    const int rowid = tid >> 1;       // 0..255
    const int r = rowid & 127;        // w
    const int half = tid & 1;
    const float* src = (rowid < 128 ? XL : XH) + half * 32 * PW + r;
    float s = 0.f, s2 = 0.f;
#pragma unroll
    for (int c = 0; c < 32; c++) {
      const float v = src[c * PW];
      s += v;
      s2 = fmaf(v, v, s2);
    }
    s += __shfl_xor_sync(0xffffffffu, s, 1);
    s2 += __shfl_xor_sync(0xffffffffu, s2, 1);
    if (half == 0) {
      const float m = s * (1.f / 64.f);
      const float var = fmaf(-m, m, s2 * (1.f / 64.f));
      const float rs = rsqrtf(var + 1e-5f);
      if (rowid < 128) { meanl[r] = m; rstdl[r] = rs; }
      else             { meanh[r] = m; rstdh[r] = rs; }
    }
  }
  load_weight_fold(Wq, g1, b1, WB, t1, t2, tid);
  __syncthreads();

  gemm_xw_mma<true>(XL, WB, QV1, wid, qr, qc, meanl, rstdl, t1, t2);
  __syncthreads();

  load_weight_fold(Wk, g2, b2, WB, t1, t2, tid);
  __syncthreads();

  gemm_xw_mma<true>(XH, WB, KV2, wid, qr, qc, meanh, rstdh, t1, t2);
  __syncthreads();

  // ---- E = exp(QK^T/8); stage Wv1 same phase ----
  gemm_s_mma(QV1, KV2, Ebuf, wid, qr, qc);
  load_weight_raw(Wv1, WB, tid);
  __syncthreads();

  // ---- row/col sums of E; V1 = XL @ Wv1^T ----
  {
    const int s_idx = tid >> 1;
    const int half = tid & 1;
    float s = 0.f;
    if (s_idx < 128) {
      const float* row = Ebuf + s_idx * PE + half * 64;
#pragma unroll 8
      for (int v = 0; v < 64; v++) s += row[v];
    } else {
      const int v = s_idx - 128;
      const float* col = Ebuf + half * 64 * PE + v;
#pragma unroll 8
      for (int i = 0; i < 64; i++) s += col[i * PE];
    }
    s += __shfl_xor_sync(0xffffffffu, s, 1);
    if (half == 0) {
      if (s_idx < 128) invrow[s_idx] = 1.f / s;
      else             invcol[s_idx - 128] = 1.f / s;
    }
  }
  gemm_xw_mma<false>(XL, WB, QV1, wid, qr, qc, nullptr, nullptr, nullptr, nullptr);
  __syncthreads();

  load_weight_raw(Wv2, WB, tid);
  __syncthreads();

  gemm_xw_mma<false>(XH, WB, KV2, wid, qr, qc, nullptr, nullptr, nullptr, nullptr);
  __syncthreads();

  // ---- out gemms ----
  gemm_out_l(Ebuf, KV2, XL, invrow, wid, qr, qc);
  gemm_out_h(Ebuf, QV1, XH, invcol, wid, qr, qc);
  __syncthreads();

  // ---- writeout: conflict-free LDS.128, coalesced STG ----
  for (int i = tid; i < kC * (kW / 4); i += NTHR) {
    const int c = i >> 5;
    const int w4 = (i & 31) * 4;
    const size_t goff = planeoff + (size_t)c * PLANE + w4;
    *(float4*)(out_l + goff) = *(const float4*)(XL + c * PW + w4);
    *(float4*)(out_h + goff) = *(const float4*)(XH + c * PW + w4);
  }
}

}  // namespace

extern "C" void kernel_launch(void* const* d_in, const int* in_sizes, int n_in,
                              void* d_out, int out_size) {
  const float* x_l = (const float*)d_in[0];
  const float* x_h = (const float*)d_in[1];
  const float* g1 = (const float*)d_in[2];
  const float* b1 = (const float*)d_in[3];
  const float* g2 = (const float*)d_in[4];
  const float* b2 = (const float*)d_in[5];
  const float* Wq = (const float*)d_in[6];
  const float* Wk = (const float*)d_in[7];
  const float* Wv1 = (const float*)d_in[8];
  const float* Wv2 = (const float*)d_in[9];

  float* out = (float*)d_out;
  float* out_l = out;
  float* out_h = out + (size_t)kB * kC * kH * kW;

  const size_t smem = (size_t)SMEM_FLOATS * sizeof(float);  // ~222.5 KB
  cudaFuncSetAttribute(scam_kernel, cudaFuncAttributeMaxDynamicSharedMemorySize, (int)smem);
  scam_kernel<<<kB * kH, NTHR, smem>>>(x_l, x_h, g1, b1, g2, b2, Wq, Wk, Wv1, Wv2,
                                       out_l, out_h);
}

// round 6
// speedup vs baseline: 3.4742x; 1.1614x over previous
#include <cuda_runtime.h>
#include <cstdint>

namespace {

constexpr int kB = 16, kC = 64, kH = 128, kW = 128;
constexpr int PX = 68;    // pitch, w-major [128 x 64] Q/K tiles; 68 % 32 == 4
constexpr int PV = 132;   // pitch, c-major [64 x 128] V tiles; 132 % 32 == 4
constexpr int PW = 136;   // pitch, c-major [64 x 128] x/out tiles; 136 % 32 == 8
constexpr int NTHR = 512;
constexpr int PLANE = kH * kW;
// E: 128x128, pitch 128, XOR-swizzled: word(r,c) = r*128 + (c ^ 8*(r&3) ^ 4*((r>>2)&1))
constexpr int SMEM_FLOATS =
    2 * 64 * PW + 2 * 128 * PX + 128 * 128 + 64 * PX + 2 * 512 + 4 * 128 + 2 * 64 + 2 * 128;

__device__ __forceinline__ uint32_t f2t(float x) {
  uint32_t r;
  asm("cvt.rna.tf32.f32 %0, %1;" : "=r"(r) : "f"(x));
  return r;
}
__device__ __forceinline__ float tround(float x) { return __uint_as_float(f2t(x)); }
__device__ __forceinline__ uint32_t fu(float x) { return __float_as_uint(x); }

__device__ __forceinline__ void mma8(float* c, uint32_t a0, uint32_t a1, uint32_t a2,
                                     uint32_t a3, uint32_t b0, uint32_t b1) {
  asm volatile(
      "mma.sync.aligned.m16n8k8.row.col.f32.tf32.tf32.f32 "
      "{%0,%1,%2,%3},{%4,%5,%6,%7},{%8,%9},{%0,%1,%2,%3};"
      : "+f"(c[0]), "+f"(c[1]), "+f"(c[2]), "+f"(c[3])
      : "r"(a0), "r"(a1), "r"(a2), "r"(a3), "r"(b0), "r"(b1));
}

__device__ __forceinline__ void load_weight_fold(
    const float* __restrict__ Wsrc, const float* __restrict__ g,
    const float* __restrict__ bb, float* __restrict__ WB,
    float* __restrict__ t1, float* __restrict__ t2, int tid) {
  const int j = tid >> 3;
  const int c0 = (tid & 7) * 8;
  float s1 = 0.f, s2 = 0.f;
#pragma unroll
  for (int u = 0; u < 8; u++) {
    const int c = c0 + u;
    const float raw = Wsrc[j * 64 + c];
    const float wf = tround(raw * g[c]);
    WB[j * PX + c] = wf;
    s1 += wf;
    s2 += raw * bb[c];
  }
  s1 += __shfl_xor_sync(0xffffffffu, s1, 1);
  s1 += __shfl_xor_sync(0xffffffffu, s1, 2);
  s1 += __shfl_xor_sync(0xffffffffu, s1, 4);
  s2 += __shfl_xor_sync(0xffffffffu, s2, 1);
  s2 += __shfl_xor_sync(0xffffffffu, s2, 2);
  s2 += __shfl_xor_sync(0xffffffffu, s2, 4);
  if ((tid & 7) == 0) { t1[j] = s1; t2[j] = s2; }
}

__device__ __forceinline__ void load_weight_raw(
    const float* __restrict__ Wsrc, float* __restrict__ WB, int tid) {
  const int j = tid >> 3;
  const int c0 = (tid & 7) * 8;
#pragma unroll
  for (int u = 0; u < 8; u++) WB[j * PX + c0 + u] = tround(Wsrc[j * 64 + c0 + u]);
}

// C[128][64] = A @ WB^T; A c-major [c][PW] (transposed frag reads, conflict-free).
// MODE 0: LN epilogue, output w-major [w][PX] (Q/K).
// MODE 1: raw, output c-major [c][PV] (V1/V2).
template <int MODE>
__device__ __forceinline__ void gemm_xw_mma(
    const float* __restrict__ A, const float* __restrict__ WB, float* __restrict__ C,
    int wid, int qr, int qc, const float* __restrict__ mean,
    const float* __restrict__ rstd, const float* __restrict__ t1,
    const float* __restrict__ t2) {
  const int r0 = (wid & 3) * 32;
  const int c0 = (wid >> 2) * 16;
  float acc[2][2][4];
#pragma unroll
  for (int mi = 0; mi < 2; mi++)
#pragma unroll
    for (int nj = 0; nj < 2; nj++)
#pragma unroll
      for (int e = 0; e < 4; e++) acc[mi][nj][e] = 0.f;

#pragma unroll
  for (int k0 = 0; k0 < 64; k0 += 8) {
    uint32_t af[2][4];
#pragma unroll
    for (int mi = 0; mi < 2; mi++) {
      const float* ap = A + (k0 + qc) * PW + r0 + mi * 16 + qr;
      af[mi][0] = f2t(ap[0]);
      af[mi][1] = f2t(ap[8]);
      af[mi][2] = f2t(ap[4 * PW]);
      af[mi][3] = f2t(ap[4 * PW + 8]);
    }
    uint32_t bf[2][2];
#pragma unroll
    for (int nj = 0; nj < 2; nj++) {
      const float* bp = WB + (c0 + nj * 8 + qr) * PX + k0 + qc;
      bf[nj][0] = fu(bp[0]);
      bf[nj][1] = fu(bp[4]);
    }
#pragma unroll
    for (int mi = 0; mi < 2; mi++)
#pragma unroll
      for (int nj = 0; nj < 2; nj++)
        mma8(acc[mi][nj], af[mi][0], af[mi][1], af[mi][2], af[mi][3], bf[nj][0], bf[nj][1]);
  }

#pragma unroll
  for (int mi = 0; mi < 2; mi++) {
    const int ra = r0 + mi * 16 + qr;
#pragma unroll
    for (int nj = 0; nj < 2; nj++) {
      const int cc = c0 + nj * 8 + 2 * qc;
      float v0 = acc[mi][nj][0], v1 = acc[mi][nj][1];
      float v2 = acc[mi][nj][2], v3 = acc[mi][nj][3];
      if (MODE == 0) {
        const float m0 = mean[ra], rs0 = rstd[ra];
        const float m1 = mean[ra + 8], rs1 = rstd[ra + 8];
        const float ta = t1[cc], tb = t1[cc + 1];
        const float ua = t2[cc], ub = t2[cc + 1];
        v0 = rs0 * (v0 - m0 * ta) + ua;
        v1 = rs0 * (v1 - m0 * tb) + ub;
        v2 = rs1 * (v2 - m1 * ta) + ua;
        v3 = rs1 * (v3 - m1 * tb) + ub;
        *(float2*)&C[ra * PX + cc] = make_float2(tround(v0), tround(v1));
        *(float2*)&C[(ra + 8) * PX + cc] = make_float2(tround(v2), tround(v3));
      } else {
        // c-major stores, conflict-free (banks = 8qc + qr)
        C[cc * PV + ra] = tround(v0);
        C[(cc + 1) * PV + ra] = tround(v1);
        C[cc * PV + ra + 8] = tround(v2);
        C[(cc + 1) * PV + ra + 8] = tround(v3);
      }
    }
  }
}

// E = exp(Q K^T / 8) -> swizzled E; also emits per-tile row/col partial sums.
__device__ __forceinline__ void gemm_s_mma(
    const float* __restrict__ Q, const float* __restrict__ K, float* __restrict__ E,
    float* __restrict__ rowp, float* __restrict__ colp, int wid, int qr, int qc,
    int swm) {
  const int r0 = (wid & 3) * 32;
  const int c0 = (wid >> 2) * 32;
  float acc[2][4][4];
#pragma unroll
  for (int mi = 0; mi < 2; mi++)
#pragma unroll
    for (int nj = 0; nj < 4; nj++)
#pragma unroll
      for (int e = 0; e < 4; e++) acc[mi][nj][e] = 0.f;

#pragma unroll
  for (int k0 = 0; k0 < 64; k0 += 8) {
    uint32_t af[2][4];
#pragma unroll
    for (int mi = 0; mi < 2; mi++) {
      const float* ap = Q + (r0 + mi * 16 + qr) * PX + k0 + qc;
      af[mi][0] = fu(ap[0]);
      af[mi][1] = fu(ap[8 * PX]);
      af[mi][2] = fu(ap[4]);
      af[mi][3] = fu(ap[8 * PX + 4]);
    }
    uint32_t bf[4][2];
#pragma unroll
    for (int nj = 0; nj < 4; nj++) {
      const float* bp = K + (c0 + nj * 8 + qr) * PX + k0 + qc;
      bf[nj][0] = fu(bp[0]);
      bf[nj][1] = fu(bp[4]);
    }
#pragma unroll
    for (int mi = 0; mi < 2; mi++)
#pragma unroll
      for (int nj = 0; nj < 4; nj++)
        mma8(acc[mi][nj], af[mi][0], af[mi][1], af[mi][2], af[mi][3], bf[nj][0], bf[nj][1]);
  }

  float rs0[2] = {0.f, 0.f}, rs1[2] = {0.f, 0.f};
  float cs0[4] = {0.f, 0.f, 0.f, 0.f}, cs1[4] = {0.f, 0.f, 0.f, 0.f};
#pragma unroll
  for (int mi = 0; mi < 2; mi++) {
    const int ra = r0 + mi * 16 + qr;
#pragma unroll
    for (int nj = 0; nj < 4; nj++) {
      const int cc = c0 + nj * 8 + 2 * qc;
      const int cS = cc ^ swm;
      const float e0 = tround(__expf(0.125f * acc[mi][nj][0]));
      const float e1 = tround(__expf(0.125f * acc[mi][nj][1]));
      const float e2 = tround(__expf(0.125f * acc[mi][nj][2]));
      const float e3 = tround(__expf(0.125f * acc[mi][nj][3]));
      *(float2*)&E[ra * 128 + cS] = make_float2(e0, e1);
      *(float2*)&E[(ra + 8) * 128 + cS] = make_float2(e2, e3);
      rs0[mi] += e0 + e1;
      rs1[mi] += e2 + e3;
      cs0[nj] += e0 + e2;
      cs1[nj] += e1 + e3;
    }
  }
  // row partials: reduce over qc (lane bits 0-1)
#pragma unroll
  for (int mi = 0; mi < 2; mi++) {
    rs0[mi] += __shfl_xor_sync(0xffffffffu, rs0[mi], 1);
    rs0[mi] += __shfl_xor_sync(0xffffffffu, rs0[mi], 2);
    rs1[mi] += __shfl_xor_sync(0xffffffffu, rs1[mi], 1);
    rs1[mi] += __shfl_xor_sync(0xffffffffu, rs1[mi], 2);
  }
  if (qc == 0) {
    float* rp = rowp + (wid >> 2) * 128;
#pragma unroll
    for (int mi = 0; mi < 2; mi++) {
      rp[r0 + mi * 16 + qr] = rs0[mi];
      rp[r0 + mi * 16 + qr + 8] = rs1[mi];
    }
  }
  // col partials: reduce over qr (lane bits 2-4)
#pragma unroll
  for (int nj = 0; nj < 4; nj++) {
    cs0[nj] += __shfl_xor_sync(0xffffffffu, cs0[nj], 4);
    cs0[nj] += __shfl_xor_sync(0xffffffffu, cs0[nj], 8);
    cs0[nj] += __shfl_xor_sync(0xffffffffu, cs0[nj], 16);
    cs1[nj] += __shfl_xor_sync(0xffffffffu, cs1[nj], 4);
    cs1[nj] += __shfl_xor_sync(0xffffffffu, cs1[nj], 8);
    cs1[nj] += __shfl_xor_sync(0xffffffffu, cs1[nj], 16);
  }
  if (qr == 0) {
    float* cp = colp + (wid & 3) * 128;
#pragma unroll
    for (int nj = 0; nj < 4; nj++) {
      cp[c0 + nj * 8 + 2 * qc] = cs0[nj];
      cp[c0 + nj * 8 + 2 * qc + 1] = cs1[nj];
    }
  }
}

// XL[c][w] += invrow[w] * (E @ V2)[w][c]. E swizzled row-reads; V2 c-major.
__device__ __forceinline__ void gemm_out_l(
    const float* __restrict__ E, const float* __restrict__ V2, float* __restrict__ XL,
    const float* __restrict__ invrow, int wid, int qr, int qc, int swm) {
  const int r0 = (wid & 3) * 32;
  const int c0 = (wid >> 2) * 16;
  float acc[2][2][4];
#pragma unroll
  for (int mi = 0; mi < 2; mi++)
#pragma unroll
    for (int nj = 0; nj < 2; nj++)
#pragma unroll
      for (int e = 0; e < 4; e++) acc[mi][nj][e] = 0.f;

#pragma unroll
  for (int k0 = 0; k0 < 128; k0 += 8) {
    const int col = (k0 + qc) ^ swm;
    uint32_t af[2][4];
#pragma unroll
    for (int mi = 0; mi < 2; mi++) {
      const int r = r0 + mi * 16 + qr;
      af[mi][0] = fu(E[r * 128 + col]);
      af[mi][1] = fu(E[(r + 8) * 128 + col]);
      af[mi][2] = fu(E[r * 128 + (col ^ 4)]);
      af[mi][3] = fu(E[(r + 8) * 128 + (col ^ 4)]);
    }
    uint32_t bf[2][2];
#pragma unroll
    for (int nj = 0; nj < 2; nj++) {
      const float* bp = V2 + (c0 + nj * 8 + qr) * PV + k0 + qc;
      bf[nj][0] = fu(bp[0]);
      bf[nj][1] = fu(bp[4]);
    }
#pragma unroll
    for (int mi = 0; mi < 2; mi++)
#pragma unroll
      for (int nj = 0; nj < 2; nj++)
        mma8(acc[mi][nj], af[mi][0], af[mi][1], af[mi][2], af[mi][3], bf[nj][0], bf[nj][1]);
  }

#pragma unroll
  for (int mi = 0; mi < 2; mi++) {
    const int ra = r0 + mi * 16 + qr;
    const float ir0 = invrow[ra], ir1 = invrow[ra + 8];
#pragma unroll
    for (int nj = 0; nj < 2; nj++) {
      const int cc = c0 + nj * 8 + 2 * qc;
      XL[cc * PW + ra] += acc[mi][nj][0] * ir0;
      XL[(cc + 1) * PW + ra] += acc[mi][nj][1] * ir0;
      XL[cc * PW + ra + 8] += acc[mi][nj][2] * ir1;
      XL[(cc + 1) * PW + ra + 8] += acc[mi][nj][3] * ir1;
    }
  }
}

// out_h^T = V1^T @ E. V1 c-major (A-frags), E swizzled col-reads (B-frags).
__device__ __forceinline__ void gemm_out_h(
    const float* __restrict__ E, const float* __restrict__ V1, float* __restrict__ XH,
    const float* __restrict__ invcol, int wid, int qr, int qc) {
  const int r0 = (wid & 3) * 16;   // c dimension (64)
  const int c0 = (wid >> 2) * 32;  // w dimension (128)
  float acc[4][4];
#pragma unroll
  for (int nj = 0; nj < 4; nj++)
#pragma unroll
    for (int e = 0; e < 4; e++) acc[nj][e] = 0.f;

  const int sw1 = 8 * qc;
#pragma unroll
  for (int k0 = 0; k0 < 128; k0 += 8) {
    const int rr = r0 + qr;
    const float* ap = V1 + rr * PV + k0 + qc;
    uint32_t a0 = fu(ap[0]);
    uint32_t a1 = fu(ap[8 * PV]);
    uint32_t a2 = fu(ap[4]);
    uint32_t a3 = fu(ap[8 * PV + 4]);
    const int rowA = (k0 + qc) * 128;
    const int rowB = (k0 + qc + 4) * 128;
    uint32_t bf[4][2];
#pragma unroll
    for (int nj = 0; nj < 4; nj++) {
      const int cc = c0 + nj * 8 + qr;
      bf[nj][0] = fu(E[rowA + (cc ^ sw1)]);
      bf[nj][1] = fu(E[rowB + (cc ^ sw1 ^ 4)]);
    }
#pragma unroll
    for (int nj = 0; nj < 4; nj++)
      mma8(acc[nj], a0, a1, a2, a3, bf[nj][0], bf[nj][1]);
  }

  const int ra = r0 + qr;  // c
#pragma unroll
  for (int nj = 0; nj < 4; nj++) {
    const int w0 = c0 + nj * 8 + 2 * qc;
    const int w1 = w0 + 1;
    XH[ra * PW + w0] += acc[nj][0] * invcol[w0];
    XH[ra * PW + w1] += acc[nj][1] * invcol[w1];
    XH[(ra + 8) * PW + w0] += acc[nj][2] * invcol[w0];
    XH[(ra + 8) * PW + w1] += acc[nj][3] * invcol[w1];
  }
}

__global__ __launch_bounds__(NTHR, 1)
void scam_kernel(const float* __restrict__ x_l, const float* __restrict__ x_h,
                 const float* __restrict__ g1, const float* __restrict__ b1,
                 const float* __restrict__ g2, const float* __restrict__ b2,
                 const float* __restrict__ Wq, const float* __restrict__ Wk,
                 const float* __restrict__ Wv1, const float* __restrict__ Wv2,
                 float* __restrict__ out_l, float* __restrict__ out_h) {
  extern __shared__ float sm[];
  float* XL = sm;                    // [64][PW] c-major fp32 residual + out stage
  float* XH = XL + 64 * PW;
  float* QV1 = XH + 64 * PW;         // Q w-major [128][PX], then V1 c-major [64][PV]
  float* KV2 = QV1 + 128 * PX;       // K, then V2
  float* Ebuf = KV2 + 128 * PX;      // [128][128] swizzled exp(attn)
  float* WB = Ebuf + 128 * 128;      // [64][PX] weight staging
  float* rowp = WB + 64 * PX;        // [4][128] row partials
  float* colp = rowp + 512;          // [4][128] col partials
  float* meanl = colp + 512;
  float* rstdl = meanl + 128;
  float* meanh = rstdl + 128;
  float* rstdh = meanh + 128;
  float* t1 = rstdh + 128;
  float* t2 = t1 + 64;
  float* invrow = t2 + 64;
  float* invcol = invrow + 128;

  const int tid = threadIdx.x;
  const int lane = tid & 31;
  const int wid = tid >> 5;
  const int qr = lane >> 2;
  const int qc = lane & 3;
  const int swm = ((qr & 3) << 3) | ((qr >> 2) << 2);  // E swizzle, f(qr) only
  const int bh = blockIdx.x;
  const int b = bh >> 7;
  const int h = bh & 127;
  const size_t planeoff = ((size_t)b * kC * kH + (size_t)h) * kW;

  // ---- load x slices, c-major float4 STS (conflict-free, coalesced) ----
  for (int i = tid; i < kC * (kW / 4); i += NTHR) {
    const int c = i >> 5;
    const int w4 = (i & 31) * 4;
    const size_t goff = planeoff + (size_t)c * PLANE + w4;
    *(float4*)(XL + c * PW + w4) = *(const float4*)(x_l + goff);
    *(float4*)(XH + c * PW + w4) = *(const float4*)(x_h + goff);
  }
  __syncthreads();

  // ---- LN stats + stage Wq ----
  {
    const int rowid = tid >> 1;
    const int r = rowid & 127;
    const int half = tid & 1;
    const float* src = (rowid < 128 ? XL : XH) + half * 32 * PW + r;
    float s = 0.f, s2 = 0.f;
#pragma unroll
    for (int c = 0; c < 32; c++) {
      const float v = src[c * PW];
      s += v;
      s2 = fmaf(v, v, s2);
    }
    s += __shfl_xor_sync(0xffffffffu, s, 1);
    s2 += __shfl_xor_sync(0xffffffffu, s2, 1);
    if (half == 0) {
      const float m = s * (1.f / 64.f);
      const float var = fmaf(-m, m, s2 * (1.f / 64.f));
      const float rs = rsqrtf(var + 1e-5f);
      if (rowid < 128) { meanl[r] = m; rstdl[r] = rs; }
      else             { meanh[r] = m; rstdh[r] = rs; }
    }
  }
  load_weight_fold(Wq, g1, b1, WB, t1, t2, tid);
  __syncthreads();

  gemm_xw_mma<0>(XL, WB, QV1, wid, qr, qc, meanl, rstdl, t1, t2);
  __syncthreads();

  load_weight_fold(Wk, g2, b2, WB, t1, t2, tid);
  __syncthreads();

  gemm_xw_mma<0>(XH, WB, KV2, wid, qr, qc, meanh, rstdh, t1, t2);
  __syncthreads();

  // ---- E = exp(QK^T/8) + in-register row/col partials; stage Wv1 ----
  gemm_s_mma(QV1, KV2, Ebuf, rowp, colp, wid, qr, qc, swm);
  load_weight_raw(Wv1, WB, tid);
  __syncthreads();

  // ---- combine partials -> inverses; V1 = XL @ Wv1^T (c-major, overwrites Q) ----
  if (tid < 128) {
    invrow[tid] = 1.f / (rowp[tid] + rowp[128 + tid] + rowp[256 + tid] + rowp[384 + tid]);
  } else if (tid < 256) {
    const int c = tid - 128;
    invcol[c] = 1.f / (colp[c] + colp[128 + c] + colp[256 + c] + colp[384 + c]);
  }
  gemm_xw_mma<1>(XL, WB, QV1, wid, qr, qc, nullptr, nullptr, nullptr, nullptr);
  __syncthreads();

  load_weight_raw(Wv2, WB, tid);
  __syncthreads();

  gemm_xw_mma<1>(XH, WB, KV2, wid, qr, qc, nullptr, nullptr, nullptr, nullptr);
  __syncthreads();

  // ---- out gemms ----
  gemm_out_l(Ebuf, KV2, XL, invrow, wid, qr, qc, swm);
  gemm_out_h(Ebuf, QV1, XH, invcol, wid, qr, qc);
  __syncthreads();

  // ---- writeout: conflict-free LDS.128, coalesced STG ----
  for (int i = tid; i < kC * (kW / 4); i += NTHR) {
    const int c = i >> 5;
    const int w4 = (i & 31) * 4;
    const size_t goff = planeoff + (size_t)c * PLANE + w4;
    *(float4*)(out_l + goff) = *(const float4*)(XL + c * PW + w4);
    *(float4*)(out_h + goff) = *(const float4*)(XH + c * PW + w4);
  }
}

}  // namespace

extern "C" void kernel_launch(void* const* d_in, const int* in_sizes, int n_in,
                              void* d_out, int out_size) {
  const float* x_l = (const float*)d_in[0];
  const float* x_h = (const float*)d_in[1];
  const float* g1 = (const float*)d_in[2];
  const float* b1 = (const float*)d_in[3];
  const float* g2 = (const float*)d_in[4];
  const float* b2 = (const float*)d_in[5];
  const float* Wq = (const float*)d_in[6];
  const float* Wk = (const float*)d_in[7];
  const float* Wv1 = (const float*)d_in[8];
  const float* Wv2 = (const float*)d_in[9];

  float* out = (float*)d_out;
  float* out_l = out;
  float* out_h = out + (size_t)kB * kC * kH * kW;

  const size_t smem = (size_t)SMEM_FLOATS * sizeof(float);  // ~224.5 KB
  cudaFuncSetAttribute(scam_kernel, cudaFuncAttributeMaxDynamicSharedMemorySize, (int)smem);
  scam_kernel<<<kB * kH, NTHR, smem>>>(x_l, x_h, g1, b1, g2, b2, Wq, Wk, Wv1, Wv2,
                                       out_l, out_h);
}